// round 3
// baseline (speedup 1.0000x reference)
#include <cuda_runtime.h>
#include <cuda_bf16.h>
#include <cstdint>

// Problem constants
#define BB 64      // batch
#define SS 64      // src length (encoder steps)
#define TD 31      // decoder steps (T-1)
#define EE 256     // embed dim
#define HH 512     // hidden
#define GG 2048    // 4*H gates
#define VV 32000   // vocab
#define NENC (SS*BB)   // 4096 rows
#define NDEC (TD*BB)   // 1984 rows

// -------- device scratch (allocation-free rule: __device__ globals) --------
__device__ float g_xp_enc[(size_t)NENC * GG];   // 33.5 MB [t*64+b][g]
__device__ float g_xp_dec[(size_t)NDEC * GG];   // 16.3 MB
__device__ float g_h[2][BB * HH];               // ping-pong hidden state
__device__ float g_c[BB * HH];                  // cell state (in-place)
__device__ float g_hseq[(size_t)NDEC * HH];     // decoder outputs [t*64+b][h]
__device__ float g_part[4][BB * GG];            // split-K partial gate sums

// ---------------------------------------------------------------------------
// init: zero out[:,0,:], h0, c0  (must run every replay; d_out is poisoned)
// ---------------------------------------------------------------------------
__global__ void init_kernel(float* __restrict__ out,
                            float* __restrict__ h0, float* __restrict__ c0) {
    long idx = (long)blockIdx.x * 256 + threadIdx.x;
    if (idx < (long)BB * VV) {
        long b = idx / VV, v = idx - b * VV;
        out[b * (32L * VV) + v] = 0.f;           // out[b][0][v]
    }
    if (idx < BB * HH) { h0[idx] = 0.f; c0[idx] = 0.f; }
}

// ---------------------------------------------------------------------------
// Generic fp32 GEMM: C[r][n] = sum_k A_eff[r][k] * Bw[n][k] (+ bias0[n]+bias1[n])
//   A_eff row = tok ? emb[tok[(r%64)*tokStride + r/64]] : A + r*lda
//   Tiles: BM=64, BN=64, inner BK=32; 256 thr, 4x4 micro-tile (stride-16).
//   blockIdx: x = n-tile, y = m-tile, z = K-split chunk (kStart = z*kLen).
// ---------------------------------------------------------------------------
__global__ __launch_bounds__(256) void gemm_fp32(
    const float* __restrict__ A, int lda,
    const int* __restrict__ tok, int tokStride,
    const float* __restrict__ Bw,
    int kLen,
    const float* __restrict__ bias0, const float* __restrict__ bias1,
    float* __restrict__ Cout, long zStride)
{
    __shared__ float As[32 * 65];
    __shared__ float Bs[32 * 65];
    const int tid = threadIdx.x;
    const int nBase = blockIdx.x * 64;
    const int rBase = blockIdx.y * 64;
    const int kStart = blockIdx.z * kLen;
    float* __restrict__ C = Cout + (long)blockIdx.z * zStride;

    const int tm0 = tid >> 4;      // 0..15
    const int tn0 = tid & 15;      // 0..15
    float acc[4][4] = {};

    const int numK = kLen >> 5;
    for (int kt = 0; kt < numK; ++kt) {
        const int k0 = kStart + (kt << 5);
#pragma unroll
        for (int it = 0; it < 2; ++it) {
            int idx = it * 256 + tid;          // 0..511
            int row = idx >> 3, q = idx & 7;   // row 0..63, q 0..7 (float4 slot)
            int r = rBase + row;
            const float* Arow;
            if (tok) {
                int tokid = tok[(r & 63) * tokStride + (r >> 6)];
                Arow = A + (long)tokid * lda;
            } else {
                Arow = A + (long)r * lda;
            }
            float4 av = *(const float4*)(Arow + k0 + q * 4);
            int sb = (q * 4) * 65 + row;
            As[sb] = av.x; As[sb + 65] = av.y; As[sb + 130] = av.z; As[sb + 195] = av.w;
            const float* Brow = Bw + (long)(nBase + row) * lda;
            float4 bv = *(const float4*)(Brow + k0 + q * 4);
            Bs[sb] = bv.x; Bs[sb + 65] = bv.y; Bs[sb + 130] = bv.z; Bs[sb + 195] = bv.w;
        }
        __syncthreads();
#pragma unroll 8
        for (int k = 0; k < 32; ++k) {
            const float* ar = &As[k * 65];
            const float* br = &Bs[k * 65];
            float a0 = ar[tm0], a1 = ar[tm0 + 16], a2 = ar[tm0 + 32], a3 = ar[tm0 + 48];
            float b0 = br[tn0], b1 = br[tn0 + 16], b2 = br[tn0 + 32], b3 = br[tn0 + 48];
            acc[0][0] += a0 * b0; acc[0][1] += a0 * b1; acc[0][2] += a0 * b2; acc[0][3] += a0 * b3;
            acc[1][0] += a1 * b0; acc[1][1] += a1 * b1; acc[1][2] += a1 * b2; acc[1][3] += a1 * b3;
            acc[2][0] += a2 * b0; acc[2][1] += a2 * b1; acc[2][2] += a2 * b2; acc[2][3] += a2 * b3;
            acc[3][0] += a3 * b0; acc[3][1] += a3 * b1; acc[3][2] += a3 * b2; acc[3][3] += a3 * b3;
        }
        __syncthreads();
    }

#pragma unroll
    for (int i = 0; i < 4; ++i) {
        int r = rBase + tm0 + 16 * i;
#pragma unroll
        for (int j = 0; j < 4; ++j) {
            int n = nBase + tn0 + 16 * j;
            float v = acc[i][j];
            if (bias0) v += bias0[n] + bias1[n];
            C[(long)r * GG + n] = v;
        }
    }
}

// ---------------------------------------------------------------------------
// LSTM pointwise: gates = xp + sum(partials); update c, h (torch i,f,g,o)
// ---------------------------------------------------------------------------
__device__ __forceinline__ float sigf(float x) { return 1.f / (1.f + __expf(-x)); }

__global__ __launch_bounds__(256) void lstm_act(
    const float* __restrict__ xp, const float* __restrict__ part,
    float* __restrict__ c, float* __restrict__ hout, float* __restrict__ hseq)
{
    int idx = blockIdx.x * 256 + threadIdx.x;   // < 32768
    int b = idx >> 9, j = idx & 511;
    int base = b * GG + j;
    float gi = xp[base], gf = xp[base + 512], gg = xp[base + 1024], go = xp[base + 1536];
#pragma unroll
    for (int s = 0; s < 4; ++s) {
        const float* p = part + (long)s * (BB * GG) + base;
        gi += p[0]; gf += p[512]; gg += p[1024]; go += p[1536];
    }
    float cn = sigf(gf) * c[idx] + sigf(gi) * tanhf(gg);
    float hn = sigf(go) * tanhf(cn);
    c[idx] = cn;
    hout[idx] = hn;
    if (hseq) hseq[idx] = hn;
}

// ---------------------------------------------------------------------------
// fc GEMM (tf32 mma.sync m16n8k8): out[b][t+1][v] = hseq[t*64+b] . fcW[v] + fcb[v]
//   BM=128, BN=128, BK=16; 256 thr = 8 warps (4 m x 2 n), warp tile 32x64.
//   Inputs pre-rounded with cvt.rna.tf32 (unbiased) -> rel err ~4e-4.
// ---------------------------------------------------------------------------
__device__ __forceinline__ float to_tf32(float x) {
    uint32_t u;
    asm("cvt.rna.tf32.f32 %0, %1;" : "=r"(u) : "f"(x));
    return __uint_as_float(u);
}

__device__ __forceinline__ void mma_tf32(float* d, const float* a, const float* b) {
    asm volatile(
        "mma.sync.aligned.m16n8k8.row.col.f32.tf32.tf32.f32 "
        "{%0,%1,%2,%3}, {%4,%5,%6,%7}, {%8,%9}, {%0,%1,%2,%3};"
        : "+f"(d[0]), "+f"(d[1]), "+f"(d[2]), "+f"(d[3])
        : "r"(__float_as_uint(a[0])), "r"(__float_as_uint(a[1])),
          "r"(__float_as_uint(a[2])), "r"(__float_as_uint(a[3])),
          "r"(__float_as_uint(b[0])), "r"(__float_as_uint(b[1])));
}

__global__ __launch_bounds__(256) void fc_tf32(
    const float* __restrict__ Ahs, const float* __restrict__ W,
    const float* __restrict__ bias, float* __restrict__ out)
{
    __shared__ float As[128 * 20];   // [row][k] stride 20 (conflict-free frags)
    __shared__ float Bs[128 * 20];
    const int tid = threadIdx.x;
    const int lane = tid & 31, w = tid >> 5;
    const int g = lane >> 2, tig = lane & 3;
    const int wm = w & 3, wn = w >> 2;
    const int mBase = blockIdx.y * 128, nBase = blockIdx.x * 128;
    const int wr = wm * 32, wc = wn * 64;

    float acc[2][8][4] = {};

    for (int kt = 0; kt < 32; ++kt) {
        const int k0 = kt * 16;
#pragma unroll
        for (int it = 0; it < 2; ++it) {
            int idx = it * 256 + tid;            // 0..511
            int row = idx >> 2, q = idx & 3;     // row 0..127, q 0..3
            int r = mBase + row; if (r > NDEC - 1) r = NDEC - 1;   // clamp (discarded later)
            float4 av = *(const float4*)(Ahs + (long)r * HH + k0 + q * 4);
            int sb = row * 20 + q * 4;
            As[sb + 0] = to_tf32(av.x); As[sb + 1] = to_tf32(av.y);
            As[sb + 2] = to_tf32(av.z); As[sb + 3] = to_tf32(av.w);
            float4 bv = *(const float4*)(W + (long)(nBase + row) * HH + k0 + q * 4);
            Bs[sb + 0] = to_tf32(bv.x); Bs[sb + 1] = to_tf32(bv.y);
            Bs[sb + 2] = to_tf32(bv.z); Bs[sb + 3] = to_tf32(bv.w);
        }
        __syncthreads();
#pragma unroll
        for (int kb = 0; kb < 2; ++kb) {
            const int kk = kb * 8;
            float a[2][4];
            float bf[8][2];
#pragma unroll
            for (int i = 0; i < 2; ++i) {
                int rr = (wr + i * 16 + g) * 20 + kk + tig;
                a[i][0] = As[rr];
                a[i][1] = As[rr + 8 * 20];
                a[i][2] = As[rr + 4];
                a[i][3] = As[rr + 8 * 20 + 4];
            }
#pragma unroll
            for (int j = 0; j < 8; ++j) {
                int rb = (wc + j * 8 + g) * 20 + kk + tig;
                bf[j][0] = Bs[rb];
                bf[j][1] = Bs[rb + 4];
            }
#pragma unroll
            for (int i = 0; i < 2; ++i)
#pragma unroll
                for (int j = 0; j < 8; ++j)
                    mma_tf32(acc[i][j], a[i], bf[j]);
        }
        __syncthreads();
    }

    // epilogue: row r -> (b = r%64, t = r/64), write out[b][t+1][n..n+1]
#pragma unroll
    for (int i = 0; i < 2; ++i) {
        int rtop = mBase + wr + i * 16 + g;
#pragma unroll
        for (int j = 0; j < 8; ++j) {
            int n = nBase + wc + j * 8 + tig * 2;
            float bb0 = bias[n], bb1 = bias[n + 1];
            if (rtop < NDEC) {
                int b = rtop & 63, t = rtop >> 6;
                float2 v = make_float2(acc[i][j][0] + bb0, acc[i][j][1] + bb1);
                *(float2*)(out + ((long)(b * 32 + t + 1)) * VV + n) = v;
            }
            int rbot = rtop + 8;
            if (rbot < NDEC) {
                int b = rbot & 63, t = rbot >> 6;
                float2 v = make_float2(acc[i][j][2] + bb0, acc[i][j][3] + bb1);
                *(float2*)(out + ((long)(b * 32 + t + 1)) * VV + n) = v;
            }
        }
    }
}

// ---------------------------------------------------------------------------
// kernel_launch: pure kernel-launch sequence on default stream (capturable)
// ---------------------------------------------------------------------------
extern "C" void kernel_launch(void* const* d_in, const int* in_sizes, int n_in,
                              void* d_out, int out_size) {
    (void)in_sizes; (void)n_in; (void)out_size;
    const int*   src     = (const int*)  d_in[0];
    const int*   tgt     = (const int*)  d_in[1];
    const float* enc_emb = (const float*)d_in[2];
    const float* dec_emb = (const float*)d_in[3];
    const float* enc_Wih = (const float*)d_in[4];
    const float* enc_Whh = (const float*)d_in[5];
    const float* enc_bih = (const float*)d_in[6];
    const float* enc_bhh = (const float*)d_in[7];
    const float* dec_Wih = (const float*)d_in[8];
    const float* dec_Whh = (const float*)d_in[9];
    const float* dec_bih = (const float*)d_in[10];
    const float* dec_bhh = (const float*)d_in[11];
    const float* fc_W    = (const float*)d_in[12];
    const float* fc_b    = (const float*)d_in[13];
    float* out = (float*)d_out;

    float *xpE, *xpD, *hb, *cb, *hs, *pt;
    cudaGetSymbolAddress((void**)&xpE, g_xp_enc);
    cudaGetSymbolAddress((void**)&xpD, g_xp_dec);
    cudaGetSymbolAddress((void**)&hb,  g_h);
    cudaGetSymbolAddress((void**)&cb,  g_c);
    cudaGetSymbolAddress((void**)&hs,  g_hseq);
    cudaGetSymbolAddress((void**)&pt,  g_part);

    // 1) zero out[:,0,:], h0, c0
    init_kernel<<<(BB * VV + 255) / 256, 256>>>(out, hb, cb);

    // 2) xp = emb[tok] @ Wih^T + (bih + bhh)   [t*64+b][g]
    gemm_fp32<<<dim3(GG / 64, NENC / 64, 1), 256>>>(
        enc_emb, EE, src, SS, enc_Wih, EE, enc_bih, enc_bhh, xpE, 0);
    gemm_fp32<<<dim3(GG / 64, NDEC / 64, 1), 256>>>(
        dec_emb, EE, tgt, 32, dec_Wih, EE, dec_bih, dec_bhh, xpD, 0);

    // 3) encoder recurrence: 64 steps, split-K=4 GEMM + fused activation
    for (int t = 0; t < SS; ++t) {
        const float* hin = hb + (t & 1) * (BB * HH);
        float* hout      = hb + ((t + 1) & 1) * (BB * HH);
        gemm_fp32<<<dim3(GG / 64, 1, 4), 256>>>(
            hin, HH, nullptr, 0, enc_Whh, 128, nullptr, nullptr, pt, (long)BB * GG);
        lstm_act<<<(BB * HH) / 256, 256>>>(
            xpE + (long)t * (BB * GG), pt, cb, hout, nullptr);
    }

    // 4) decoder recurrence: 31 steps, record h_seq
    for (int t = 0; t < TD; ++t) {
        const float* hin = hb + (t & 1) * (BB * HH);
        float* hout      = hb + ((t + 1) & 1) * (BB * HH);
        gemm_fp32<<<dim3(GG / 64, 1, 4), 256>>>(
            hin, HH, nullptr, 0, dec_Whh, 128, nullptr, nullptr, pt, (long)BB * GG);
        lstm_act<<<(BB * HH) / 256, 256>>>(
            xpD + (long)t * (BB * GG), pt, cb, hout, hs + (long)t * (BB * HH));
    }

    // 5) vocab projection (tf32 tensor cores) -> out[b][t+1][v]
    fc_tf32<<<dim3(VV / 128, (NDEC + 127) / 128), 256>>>(hs, fc_W, fc_b, out);
}

// round 4
// speedup vs baseline: 1.3489x; 1.3489x over previous
#include <cuda_runtime.h>
#include <cuda_bf16.h>
#include <cstdint>

// Problem constants
#define BB 64      // batch
#define SS 64      // src length (encoder steps)
#define TD 31      // decoder steps (T-1)
#define EE 256     // embed dim
#define HH 512     // hidden
#define GG 2048    // 4*H gates
#define VV 32000   // vocab
#define NENC (SS*BB)   // 4096 rows
#define NDEC (TD*BB)   // 1984 rows
#define NSTEP (SS+TD)  // 95
#define RGRID 128      // recurrence CTAs (<= SM count -> co-resident)

// -------- device scratch (allocation-free rule: __device__ globals) --------
__device__ float g_xp_enc[(size_t)NENC * GG];   // 33.5 MB [t*64+b][g]
__device__ float g_xp_dec[(size_t)NDEC * GG];   // 16.3 MB
__device__ float g_h[2][BB * HH];               // ping-pong hidden state
__device__ float g_hseq[(size_t)NDEC * HH];     // decoder outputs [t*64+b][h]

// grid-barrier state: cumulative counters -> replay-safe without reset
__device__ unsigned g_arrive;
__device__ volatile unsigned g_epoch;

// ---------------------------------------------------------------------------
// init: zero out[:,0,:]  (must run every replay; d_out is poisoned)
// ---------------------------------------------------------------------------
__global__ void init_kernel(float* __restrict__ out) {
    long idx = (long)blockIdx.x * 256 + threadIdx.x;
    if (idx < (long)BB * VV) {
        long b = idx / VV, v = idx - b * VV;
        out[b * (32L * VV) + v] = 0.f;           // out[b][0][v]
    }
}

// ---------------------------------------------------------------------------
// Generic fp32 GEMM for xp: C[r][n] = emb[tok[r]] . Wih[n] + (bih[n]+bhh[n])
//   Tiles: BM=64, BN=64, inner BK=32; 256 thr, 4x4 micro-tile (stride-16).
// ---------------------------------------------------------------------------
__global__ __launch_bounds__(256) void gemm_fp32(
    const float* __restrict__ A, int lda,
    const int* __restrict__ tok, int tokStride,
    const float* __restrict__ Bw,
    const float* __restrict__ bias0, const float* __restrict__ bias1,
    float* __restrict__ Cout)
{
    __shared__ float As[32 * 65];
    __shared__ float Bs[32 * 65];
    const int tid = threadIdx.x;
    const int nBase = blockIdx.x * 64;
    const int rBase = blockIdx.y * 64;

    const int tm0 = tid >> 4;      // 0..15
    const int tn0 = tid & 15;      // 0..15
    float acc[4][4] = {};

    const int numK = lda >> 5;
    for (int kt = 0; kt < numK; ++kt) {
        const int k0 = kt << 5;
#pragma unroll
        for (int it = 0; it < 2; ++it) {
            int idx = it * 256 + tid;          // 0..511
            int row = idx >> 3, q = idx & 7;   // row 0..63, q 0..7 (float4 slot)
            int r = rBase + row;
            int tokid = tok[(r & 63) * tokStride + (r >> 6)];
            const float* Arow = A + (long)tokid * lda;
            float4 av = *(const float4*)(Arow + k0 + q * 4);
            int sb = (q * 4) * 65 + row;
            As[sb] = av.x; As[sb + 65] = av.y; As[sb + 130] = av.z; As[sb + 195] = av.w;
            const float* Brow = Bw + (long)(nBase + row) * lda;
            float4 bv = *(const float4*)(Brow + k0 + q * 4);
            Bs[sb] = bv.x; Bs[sb + 65] = bv.y; Bs[sb + 130] = bv.z; Bs[sb + 195] = bv.w;
        }
        __syncthreads();
#pragma unroll 8
        for (int k = 0; k < 32; ++k) {
            const float* ar = &As[k * 65];
            const float* br = &Bs[k * 65];
            float a0 = ar[tm0], a1 = ar[tm0 + 16], a2 = ar[tm0 + 32], a3 = ar[tm0 + 48];
            float b0 = br[tn0], b1 = br[tn0 + 16], b2 = br[tn0 + 32], b3 = br[tn0 + 48];
            acc[0][0] += a0 * b0; acc[0][1] += a0 * b1; acc[0][2] += a0 * b2; acc[0][3] += a0 * b3;
            acc[1][0] += a1 * b0; acc[1][1] += a1 * b1; acc[1][2] += a1 * b2; acc[1][3] += a1 * b3;
            acc[2][0] += a2 * b0; acc[2][1] += a2 * b1; acc[2][2] += a2 * b2; acc[2][3] += a2 * b3;
            acc[3][0] += a3 * b0; acc[3][1] += a3 * b1; acc[3][2] += a3 * b2; acc[3][3] += a3 * b3;
        }
        __syncthreads();
    }

#pragma unroll
    for (int i = 0; i < 4; ++i) {
        int r = rBase + tm0 + 16 * i;
#pragma unroll
        for (int j = 0; j < 4; ++j) {
            int n = nBase + tn0 + 16 * j;
            C_WRITE:
            Cout[(long)r * GG + n] = acc[i][j] + bias0[n] + bias1[n];
        }
    }
}

// ---------------------------------------------------------------------------
// Persistent fused LSTM recurrence (encoder 64 steps + decoder 31 steps).
//   grid = 128 CTAs x 256 thr; CTA owns hidden units [4*bx, 4*bx+4).
//   SMEM: w_s[16][516] weight slice (resident per phase),
//         h_s[64][516] staged h per step, c_s[256] resident cell state.
//   Thread (r, d): computes gates i,f,g,o of (row r, unit J+d) -> local act.
//   One software grid barrier per step (all CTAs co-resident: grid<=SMs).
// ---------------------------------------------------------------------------
__device__ __forceinline__ float sigf(float x) { return 1.f / (1.f + __expf(-x)); }

__device__ __forceinline__ void grid_sync() {
    __syncthreads();
    if (threadIdx.x == 0) {
        __threadfence();
        unsigned t = atomicAdd(&g_arrive, 1u);
        unsigned target = t / (unsigned)RGRID + 1u;
        if ((t % (unsigned)RGRID) == (unsigned)(RGRID - 1)) {
            g_epoch = target;                     // release
        } else {
            while (g_epoch < target) { __nanosleep(32); }
        }
        __threadfence();
    }
    __syncthreads();
}

#define WS_STRIDE 516
#define WS_FLOATS (16 * WS_STRIDE)
#define HS_FLOATS (64 * WS_STRIDE)

__global__ __launch_bounds__(256, 1) void lstm_persistent(
    const float* __restrict__ xpE, const float* __restrict__ xpD,
    const float* __restrict__ Wenc, const float* __restrict__ Wdec,
    float* __restrict__ hbuf, float* __restrict__ hseq)
{
    extern __shared__ float sm[];
    float* w_s = sm;                    // 16 x 516
    float* h_s = sm + WS_FLOATS;        // 64 x 516
    float* c_s = h_s + HS_FLOATS;       // 256

    const int tid  = threadIdx.x;
    const int lane = tid & 31;
    const int r    = (tid >> 5) * 8 + (lane >> 2);  // 0..63 (batch row)
    const int d    = lane & 3;                      // hidden unit within CTA
    const int J    = blockIdx.x * 4;                // hidden base

    // load encoder weight slice: w_s[(g*4+d)][k] = Whh[g*512 + J + d][k]
    for (int i = tid; i < 16 * 128; i += 256) {
        int c = i >> 7, q = (i & 127) << 2;
        int row = (c >> 2) * 512 + J + (c & 3);
        *(float4*)(w_s + c * WS_STRIDE + q) = *(const float4*)(Wenc + (long)row * HH + q);
    }
    // h0 = 0 (this CTA's slice), c0 = 0
    hbuf[(long)r * HH + J + d] = 0.f;
    c_s[tid] = 0.f;
    grid_sync();

    for (int t = 0; t < NSTEP; ++t) {
        // xp loads issued early (DRAM latency hidden behind h staging)
        const float* xp_t = (t < SS) ? (xpE + (long)t * (BB * GG))
                                     : (xpD + (long)(t - SS) * (BB * GG));
        const long xb = (long)r * GG + J + d;
        float a0 = xp_t[xb];
        float a1 = xp_t[xb + 512];
        float a2 = xp_t[xb + 1024];
        float a3 = xp_t[xb + 1536];

        // stage h[t] into SMEM (padded stride kills bank conflicts)
        const float* hin = hbuf + (t & 1) * (BB * HH);
        for (int i = tid; i < 64 * 128; i += 256) {
            int rr = i >> 7, q = (i & 127) << 2;
            *(float4*)(h_s + rr * WS_STRIDE + q) = *(const float4*)(hin + rr * HH + q);
        }
        if (t == SS) {  // switch to decoder weights (prev grid_sync ordered all reads)
            for (int i = tid; i < 16 * 128; i += 256) {
                int c = i >> 7, q = (i & 127) << 2;
                int row = (c >> 2) * 512 + J + (c & 3);
                *(float4*)(w_s + c * WS_STRIDE + q) = *(const float4*)(Wdec + (long)row * HH + q);
            }
        }
        __syncthreads();

        // gates: a[g] += h[r][:] . Whh[g*512+J+d][:]
        const float* hr  = h_s + r * WS_STRIDE;
        const float* wp0 = w_s + (0  + d) * WS_STRIDE;
        const float* wp1 = w_s + (4  + d) * WS_STRIDE;
        const float* wp2 = w_s + (8  + d) * WS_STRIDE;
        const float* wp3 = w_s + (12 + d) * WS_STRIDE;
#pragma unroll 4
        for (int k = 0; k < HH; k += 4) {
            float4 hv = *(const float4*)(hr + k);
            float4 w0 = *(const float4*)(wp0 + k);
            float4 w1 = *(const float4*)(wp1 + k);
            float4 w2 = *(const float4*)(wp2 + k);
            float4 w3 = *(const float4*)(wp3 + k);
            a0 += hv.x * w0.x; a0 += hv.y * w0.y; a0 += hv.z * w0.z; a0 += hv.w * w0.w;
            a1 += hv.x * w1.x; a1 += hv.y * w1.y; a1 += hv.z * w1.z; a1 += hv.w * w1.w;
            a2 += hv.x * w2.x; a2 += hv.y * w2.y; a2 += hv.z * w2.z; a2 += hv.w * w2.w;
            a3 += hv.x * w3.x; a3 += hv.y * w3.y; a3 += hv.z * w3.z; a3 += hv.w * w3.w;
        }

        // activation (torch order i,f,g,o), c resident in SMEM
        float cn = sigf(a1) * c_s[tid] + sigf(a0) * tanhf(a2);
        float hn = sigf(a3) * tanhf(cn);
        c_s[tid] = cn;

        float* hout = hbuf + ((t + 1) & 1) * (BB * HH);
        hout[(long)r * HH + J + d] = hn;
        if (t >= SS)
            hseq[(long)(t - SS) * (BB * HH) + (long)r * HH + J + d] = hn;

        grid_sync();   // h[t+1] fully visible before step t+1 reads it
    }
}

// ---------------------------------------------------------------------------
// fc GEMM (tf32 mma.sync m16n8k8): out[b][t+1][v] = hseq[t*64+b] . fcW[v] + fcb[v]
// ---------------------------------------------------------------------------
__device__ __forceinline__ float to_tf32(float x) {
    uint32_t u;
    asm("cvt.rna.tf32.f32 %0, %1;" : "=r"(u) : "f"(x));
    return __uint_as_float(u);
}

__device__ __forceinline__ void mma_tf32(float* dd, const float* a, const float* b) {
    asm volatile(
        "mma.sync.aligned.m16n8k8.row.col.f32.tf32.tf32.f32 "
        "{%0,%1,%2,%3}, {%4,%5,%6,%7}, {%8,%9}, {%0,%1,%2,%3};"
        : "+f"(dd[0]), "+f"(dd[1]), "+f"(dd[2]), "+f"(dd[3])
        : "r"(__float_as_uint(a[0])), "r"(__float_as_uint(a[1])),
          "r"(__float_as_uint(a[2])), "r"(__float_as_uint(a[3])),
          "r"(__float_as_uint(b[0])), "r"(__float_as_uint(b[1])));
}

__global__ __launch_bounds__(256) void fc_tf32(
    const float* __restrict__ Ahs, const float* __restrict__ W,
    const float* __restrict__ bias, float* __restrict__ out)
{
    __shared__ float As[128 * 20];   // [row][k] stride 20 (conflict-free frags)
    __shared__ float Bs[128 * 20];
    const int tid = threadIdx.x;
    const int lane = tid & 31, w = tid >> 5;
    const int g = lane >> 2, tig = lane & 3;
    const int wm = w & 3, wn = w >> 2;
    const int mBase = blockIdx.y * 128, nBase = blockIdx.x * 128;
    const int wr = wm * 32, wc = wn * 64;

    float acc[2][8][4] = {};

    for (int kt = 0; kt < 32; ++kt) {
        const int k0 = kt * 16;
#pragma unroll
        for (int it = 0; it < 2; ++it) {
            int idx = it * 256 + tid;            // 0..511
            int row = idx >> 2, q = idx & 3;     // row 0..127, q 0..3
            int r = mBase + row; if (r > NDEC - 1) r = NDEC - 1;   // clamp (discarded later)
            float4 av = *(const float4*)(Ahs + (long)r * HH + k0 + q * 4);
            int sb = row * 20 + q * 4;
            As[sb + 0] = to_tf32(av.x); As[sb + 1] = to_tf32(av.y);
            As[sb + 2] = to_tf32(av.z); As[sb + 3] = to_tf32(av.w);
            float4 bv = *(const float4*)(W + (long)(nBase + row) * HH + k0 + q * 4);
            Bs[sb + 0] = to_tf32(bv.x); Bs[sb + 1] = to_tf32(bv.y);
            Bs[sb + 2] = to_tf32(bv.z); Bs[sb + 3] = to_tf32(bv.w);
        }
        __syncthreads();
#pragma unroll
        for (int kb = 0; kb < 2; ++kb) {
            const int kk = kb * 8;
            float a[2][4];
            float bf[8][2];
#pragma unroll
            for (int i = 0; i < 2; ++i) {
                int rr = (wr + i * 16 + g) * 20 + kk + tig;
                a[i][0] = As[rr];
                a[i][1] = As[rr + 8 * 20];
                a[i][2] = As[rr + 4];
                a[i][3] = As[rr + 8 * 20 + 4];
            }
#pragma unroll
            for (int j = 0; j < 8; ++j) {
                int rb = (wc + j * 8 + g) * 20 + kk + tig;
                bf[j][0] = Bs[rb];
                bf[j][1] = Bs[rb + 4];
            }
#pragma unroll
            for (int i = 0; i < 2; ++i)
#pragma unroll
                for (int j = 0; j < 8; ++j)
                    mma_tf32(acc[i][j], a[i], bf[j]);
        }
        __syncthreads();
    }

    // epilogue: row r -> (b = r%64, t = r/64), write out[b][t+1][n..n+1]
#pragma unroll
    for (int i = 0; i < 2; ++i) {
        int rtop = mBase + wr + i * 16 + g;
#pragma unroll
        for (int j = 0; j < 8; ++j) {
            int n = nBase + wc + j * 8 + tig * 2;
            float bb0 = bias[n], bb1 = bias[n + 1];
            if (rtop < NDEC) {
                int b = rtop & 63, t = rtop >> 6;
                float2 v = make_float2(acc[i][j][0] + bb0, acc[i][j][1] + bb1);
                *(float2*)(out + ((long)(b * 32 + t + 1)) * VV + n) = v;
            }
            int rbot = rtop + 8;
            if (rbot < NDEC) {
                int b = rbot & 63, t = rbot >> 6;
                float2 v = make_float2(acc[i][j][2] + bb0, acc[i][j][3] + bb1);
                *(float2*)(out + ((long)(b * 32 + t + 1)) * VV + n) = v;
            }
        }
    }
}

// ---------------------------------------------------------------------------
// kernel_launch: 5 graph nodes total (init, 2 xp GEMMs, recurrence, fc)
// ---------------------------------------------------------------------------
extern "C" void kernel_launch(void* const* d_in, const int* in_sizes, int n_in,
                              void* d_out, int out_size) {
    (void)in_sizes; (void)n_in; (void)out_size;
    const int*   src     = (const int*)  d_in[0];
    const int*   tgt     = (const int*)  d_in[1];
    const float* enc_emb = (const float*)d_in[2];
    const float* dec_emb = (const float*)d_in[3];
    const float* enc_Wih = (const float*)d_in[4];
    const float* enc_Whh = (const float*)d_in[5];
    const float* enc_bih = (const float*)d_in[6];
    const float* enc_bhh = (const float*)d_in[7];
    const float* dec_Wih = (const float*)d_in[8];
    const float* dec_Whh = (const float*)d_in[9];
    const float* dec_bih = (const float*)d_in[10];
    const float* dec_bhh = (const float*)d_in[11];
    const float* fc_W    = (const float*)d_in[12];
    const float* fc_b    = (const float*)d_in[13];
    float* out = (float*)d_out;

    float *xpE, *xpD, *hb, *hs;
    cudaGetSymbolAddress((void**)&xpE, g_xp_enc);
    cudaGetSymbolAddress((void**)&xpD, g_xp_dec);
    cudaGetSymbolAddress((void**)&hb,  g_h);
    cudaGetSymbolAddress((void**)&hs,  g_hseq);

    const int smemBytes = (WS_FLOATS + HS_FLOATS + 256) * sizeof(float);  // ~166 KB
    cudaFuncSetAttribute(lstm_persistent,
                         cudaFuncAttributeMaxDynamicSharedMemorySize, smemBytes);

    // 1) zero out[:,0,:]
    init_kernel<<<(BB * VV + 255) / 256, 256>>>(out);

    // 2) xp = emb[tok] @ Wih^T + (bih + bhh)   [t*64+b][g]
    gemm_fp32<<<dim3(GG / 64, NENC / 64), 256>>>(
        enc_emb, EE, src, SS, enc_Wih, enc_bih, enc_bhh, xpE);
    gemm_fp32<<<dim3(GG / 64, NDEC / 64), 256>>>(
        dec_emb, EE, tgt, 32, dec_Wih, dec_bih, dec_bhh, xpD);

    // 3) fused persistent recurrence: enc 64 + dec 31 steps, 1 launch
    lstm_persistent<<<RGRID, 256, smemBytes>>>(xpE, xpD, enc_Whh, dec_Whh, hb, hs);

    // 4) vocab projection (tf32 tensor cores) -> out[b][t+1][v]
    fc_tf32<<<dim3(VV / 128, (NDEC + 127) / 128), 256>>>(hs, fc_W, fc_b, out);
}

// round 5
// speedup vs baseline: 1.4673x; 1.0877x over previous
#include <cuda_runtime.h>
#include <cuda_bf16.h>
#include <cstdint>

// Problem constants
#define BB 64      // batch
#define SS 64      // src length (encoder steps)
#define TD 31      // decoder steps (T-1)
#define EE 256     // embed dim
#define HH 512     // hidden
#define GG 2048    // 4*H gates
#define VV 32000   // vocab
#define NENC (SS*BB)   // 4096 rows
#define NDEC (TD*BB)   // 1984 rows
#define NSTEP (SS+TD)  // 95
#define RGRID 128      // recurrence CTAs (<= SM count -> co-resident)

// -------- device scratch (allocation-free rule: __device__ globals) --------
__device__ float g_xp_enc[(size_t)NENC * GG];   // 33.5 MB [t*64+b][g]
__device__ float g_xp_dec[(size_t)NDEC * GG];   // 16.3 MB
__device__ float g_h[2][BB * HH];               // ping-pong hidden state
__device__ float g_hseq[(size_t)NDEC * HH];     // decoder outputs [t*64+b][h]

// grid-barrier state: cumulative counters -> replay-safe without reset
__device__ unsigned g_arrive;
__device__ volatile unsigned g_epoch;

// ---------------------------------------------------------------------------
// init: zero out[:,0,:]  (must run every replay; d_out is poisoned)
// ---------------------------------------------------------------------------
__global__ void init_kernel(float* __restrict__ out) {
    long idx = (long)blockIdx.x * 256 + threadIdx.x;
    if (idx < (long)BB * VV) {
        long b = idx / VV, v = idx - b * VV;
        out[b * (32L * VV) + v] = 0.f;           // out[b][0][v]
    }
}

// ---------------------------------------------------------------------------
// Generic fp32 GEMM for xp: C[r][n] = emb[tok[r]] . Wih[n] + (bih[n]+bhh[n])
// ---------------------------------------------------------------------------
__global__ __launch_bounds__(256) void gemm_fp32(
    const float* __restrict__ A, int lda,
    const int* __restrict__ tok, int tokStride,
    const float* __restrict__ Bw,
    const float* __restrict__ bias0, const float* __restrict__ bias1,
    float* __restrict__ Cout)
{
    __shared__ float As[32 * 65];
    __shared__ float Bs[32 * 65];
    const int tid = threadIdx.x;
    const int nBase = blockIdx.x * 64;
    const int rBase = blockIdx.y * 64;

    const int tm0 = tid >> 4;      // 0..15
    const int tn0 = tid & 15;      // 0..15
    float acc[4][4] = {};

    const int numK = lda >> 5;
    for (int kt = 0; kt < numK; ++kt) {
        const int k0 = kt << 5;
#pragma unroll
        for (int it = 0; it < 2; ++it) {
            int idx = it * 256 + tid;          // 0..511
            int row = idx >> 3, q = idx & 7;   // row 0..63, q 0..7 (float4 slot)
            int r = rBase + row;
            int tokid = tok[(r & 63) * tokStride + (r >> 6)];
            const float* Arow = A + (long)tokid * lda;
            float4 av = *(const float4*)(Arow + k0 + q * 4);
            int sb = (q * 4) * 65 + row;
            As[sb] = av.x; As[sb + 65] = av.y; As[sb + 130] = av.z; As[sb + 195] = av.w;
            const float* Brow = Bw + (long)(nBase + row) * lda;
            float4 bv = *(const float4*)(Brow + k0 + q * 4);
            Bs[sb] = bv.x; Bs[sb + 65] = bv.y; Bs[sb + 130] = bv.z; Bs[sb + 195] = bv.w;
        }
        __syncthreads();
#pragma unroll 8
        for (int k = 0; k < 32; ++k) {
            const float* ar = &As[k * 65];
            const float* br = &Bs[k * 65];
            float a0 = ar[tm0], a1 = ar[tm0 + 16], a2 = ar[tm0 + 32], a3 = ar[tm0 + 48];
            float b0 = br[tn0], b1 = br[tn0 + 16], b2 = br[tn0 + 32], b3 = br[tn0 + 48];
            acc[0][0] += a0 * b0; acc[0][1] += a0 * b1; acc[0][2] += a0 * b2; acc[0][3] += a0 * b3;
            acc[1][0] += a1 * b0; acc[1][1] += a1 * b1; acc[1][2] += a1 * b2; acc[1][3] += a1 * b3;
            acc[2][0] += a2 * b0; acc[2][1] += a2 * b1; acc[2][2] += a2 * b2; acc[2][3] += a2 * b3;
            acc[3][0] += a3 * b0; acc[3][1] += a3 * b1; acc[3][2] += a3 * b2; acc[3][3] += a3 * b3;
        }
        __syncthreads();
    }

#pragma unroll
    for (int i = 0; i < 4; ++i) {
        int r = rBase + tm0 + 16 * i;
#pragma unroll
        for (int j = 0; j < 4; ++j) {
            int n = nBase + tn0 + 16 * j;
            Cout[(long)r * GG + n] = acc[i][j] + bias0[n] + bias1[n];
        }
    }
}

// ---------------------------------------------------------------------------
// Persistent fused LSTM recurrence (encoder 64 steps + decoder 31 steps).
//   grid = 128 CTAs x 256 thr; CTA owns hidden units [4*bx, 4*bx+4).
//   f32x2 packed FMA (2x fp32 MAC rate), cp.async 2-chunk staging pipeline.
// ---------------------------------------------------------------------------
__device__ __forceinline__ float sigf(float x) { return 1.f / (1.f + __expf(-x)); }

__device__ __forceinline__ void grid_sync() {
    __syncthreads();
    if (threadIdx.x == 0) {
        __threadfence();
        unsigned t = atomicAdd(&g_arrive, 1u);
        unsigned target = t / (unsigned)RGRID + 1u;
        if ((t % (unsigned)RGRID) == (unsigned)(RGRID - 1)) {
            g_epoch = target;                     // release
        } else {
            while (g_epoch < target) { }          // tight spin (L2 RTT-paced)
        }
        __threadfence();
    }
    __syncthreads();
}

__device__ __forceinline__ void cp16(float* smem, const float* gmem) {
    unsigned s = (unsigned)__cvta_generic_to_shared(smem);
    asm volatile("cp.async.ca.shared.global [%0], [%1], 16;" :: "r"(s), "l"(gmem));
}
#define CP_COMMIT() asm volatile("cp.async.commit_group;")
#define CP_WAIT(n)  asm volatile("cp.async.wait_group %0;" :: "n"(n))

#define FMA2(acc, a, b) \
    asm("fma.rn.f32x2 %0, %1, %2, %0;" : "+l"(acc) : "l"(a), "l"(b))

__device__ __forceinline__ float2 unpack2(unsigned long long v) {
    float2 f;
    asm("mov.b64 {%0, %1}, %2;" : "=f"(f.x), "=f"(f.y) : "l"(v));
    return f;
}

#define WS_STRIDE 516
#define WS_FLOATS (16 * WS_STRIDE)
#define HS_FLOATS (64 * WS_STRIDE)

__global__ __launch_bounds__(256, 1) void lstm_persistent(
    const float* __restrict__ xpE, const float* __restrict__ xpD,
    const float* __restrict__ Wenc, const float* __restrict__ Wdec,
    float* __restrict__ hbuf, float* __restrict__ hseq)
{
    extern __shared__ float sm[];
    float* w_s = sm;                    // 16 x 516
    float* h_s = sm + WS_FLOATS;        // 64 x 516
    float* c_s = h_s + HS_FLOATS;       // 256

    const int tid  = threadIdx.x;
    const int lane = tid & 31;
    const int r    = (tid >> 5) * 8 + (lane >> 2);  // 0..63 (batch row)
    const int d    = lane & 3;                      // hidden unit within CTA
    const int J    = blockIdx.x * 4;                // hidden base

    // load encoder weight slice: w_s[(g*4+d)][k] = Whh[g*512 + J + d][k]
    for (int i = tid; i < 16 * 128; i += 256) {
        int c = i >> 7, q = (i & 127) << 2;
        int row = (c >> 2) * 512 + J + (c & 3);
        *(float4*)(w_s + c * WS_STRIDE + q) = *(const float4*)(Wenc + (long)row * HH + q);
    }
    // h0 = 0 (this CTA's slice), c0 = 0
    hbuf[(long)r * HH + J + d] = 0.f;
    c_s[tid] = 0.f;
    grid_sync();

    const float* hr  = h_s + r * WS_STRIDE;
    const float* wp0 = w_s + (0  + d) * WS_STRIDE;
    const float* wp1 = w_s + (4  + d) * WS_STRIDE;
    const float* wp2 = w_s + (8  + d) * WS_STRIDE;
    const float* wp3 = w_s + (12 + d) * WS_STRIDE;

    for (int t = 0; t < NSTEP; ++t) {
        // xp loads issued early (DRAM latency hidden behind staging/compute)
        const float* xp_t = (t < SS) ? (xpE + (long)t * (BB * GG))
                                     : (xpD + (long)(t - SS) * (BB * GG));
        const long xb = (long)r * GG + J + d;
        float a0 = xp_t[xb];
        float a1 = xp_t[xb + 512];
        float a2 = xp_t[xb + 1024];
        float a3 = xp_t[xb + 1536];

        // stage h[t] into SMEM in two 256-col chunks via cp.async
        const float* hin = hbuf + (t & 1) * (BB * HH);
#pragma unroll
        for (int c = 0; c < 2; ++c) {
#pragma unroll
            for (int i = 0; i < 16; ++i) {
                int idx = i * 256 + tid;                 // 0..4095
                int rr = idx >> 6, q = (idx & 63) << 2;  // row, float offset in chunk
                cp16(h_s + rr * WS_STRIDE + c * 256 + q,
                     hin + rr * HH + c * 256 + q);
            }
            CP_COMMIT();
        }
        if (t == SS) {  // switch to decoder weights (prev grid_sync ordered reads)
            for (int i = tid; i < 16 * 128; i += 256) {
                int c = i >> 7, q = (i & 127) << 2;
                int row = (c >> 2) * 512 + J + (c & 3);
                *(float4*)(w_s + c * WS_STRIDE + q) = *(const float4*)(Wdec + (long)row * HH + q);
            }
        }

        // packed f32x2 accumulators (two k-lanes each)
        unsigned long long A0a = 0, A0b = 0, A1a = 0, A1b = 0;
        unsigned long long A2a = 0, A2b = 0, A3a = 0, A3b = 0;

        CP_WAIT(1);          // chunk 0 landed
        __syncthreads();     // (also publishes w_s reload at t==SS)
#pragma unroll 4
        for (int k = 0; k < 256; k += 4) {
            ulonglong2 hv = *(const ulonglong2*)(hr + k);
            ulonglong2 w0 = *(const ulonglong2*)(wp0 + k);
            ulonglong2 w1 = *(const ulonglong2*)(wp1 + k);
            ulonglong2 w2 = *(const ulonglong2*)(wp2 + k);
            ulonglong2 w3 = *(const ulonglong2*)(wp3 + k);
            FMA2(A0a, hv.x, w0.x); FMA2(A0b, hv.y, w0.y);
            FMA2(A1a, hv.x, w1.x); FMA2(A1b, hv.y, w1.y);
            FMA2(A2a, hv.x, w2.x); FMA2(A2b, hv.y, w2.y);
            FMA2(A3a, hv.x, w3.x); FMA2(A3b, hv.y, w3.y);
        }
        CP_WAIT(0);          // chunk 1 landed
        __syncthreads();
#pragma unroll 4
        for (int k = 256; k < 512; k += 4) {
            ulonglong2 hv = *(const ulonglong2*)(hr + k);
            ulonglong2 w0 = *(const ulonglong2*)(wp0 + k);
            ulonglong2 w1 = *(const ulonglong2*)(wp1 + k);
            ulonglong2 w2 = *(const ulonglong2*)(wp2 + k);
            ulonglong2 w3 = *(const ulonglong2*)(wp3 + k);
            FMA2(A0a, hv.x, w0.x); FMA2(A0b, hv.y, w0.y);
            FMA2(A1a, hv.x, w1.x); FMA2(A1b, hv.y, w1.y);
            FMA2(A2a, hv.x, w2.x); FMA2(A2b, hv.y, w2.y);
            FMA2(A3a, hv.x, w3.x); FMA2(A3b, hv.y, w3.y);
        }

        // reduce packed lanes and add xp
        float2 p, q2;
        p = unpack2(A0a); q2 = unpack2(A0b);
        float gi = a0 + ((p.x + q2.x) + (p.y + q2.y));
        p = unpack2(A1a); q2 = unpack2(A1b);
        float gf = a1 + ((p.x + q2.x) + (p.y + q2.y));
        p = unpack2(A2a); q2 = unpack2(A2b);
        float gg = a2 + ((p.x + q2.x) + (p.y + q2.y));
        p = unpack2(A3a); q2 = unpack2(A3b);
        float go = a3 + ((p.x + q2.x) + (p.y + q2.y));

        // activation (torch order i,f,g,o), c resident in SMEM
        float cn = sigf(gf) * c_s[tid] + sigf(gi) * tanhf(gg);
        float hn = sigf(go) * tanhf(cn);
        c_s[tid] = cn;

        float* hout = hbuf + ((t + 1) & 1) * (BB * HH);
        hout[(long)r * HH + J + d] = hn;
        if (t >= SS)
            hseq[(long)(t - SS) * (BB * HH) + (long)r * HH + J + d] = hn;

        grid_sync();   // h[t+1] fully visible before step t+1 reads it
    }
}

// ---------------------------------------------------------------------------
// fc GEMM (tf32 mma.sync m16n8k8): out[b][t+1][v] = hseq[t*64+b] . fcW[v] + fcb[v]
// ---------------------------------------------------------------------------
__device__ __forceinline__ float to_tf32(float x) {
    uint32_t u;
    asm("cvt.rna.tf32.f32 %0, %1;" : "=r"(u) : "f"(x));
    return __uint_as_float(u);
}

__device__ __forceinline__ void mma_tf32(float* dd, const float* a, const float* b) {
    asm volatile(
        "mma.sync.aligned.m16n8k8.row.col.f32.tf32.tf32.f32 "
        "{%0,%1,%2,%3}, {%4,%5,%6,%7}, {%8,%9}, {%0,%1,%2,%3};"
        : "+f"(dd[0]), "+f"(dd[1]), "+f"(dd[2]), "+f"(dd[3])
        : "r"(__float_as_uint(a[0])), "r"(__float_as_uint(a[1])),
          "r"(__float_as_uint(a[2])), "r"(__float_as_uint(a[3])),
          "r"(__float_as_uint(b[0])), "r"(__float_as_uint(b[1])));
}

__global__ __launch_bounds__(256) void fc_tf32(
    const float* __restrict__ Ahs, const float* __restrict__ W,
    const float* __restrict__ bias, float* __restrict__ out)
{
    __shared__ float As[128 * 20];   // [row][k] stride 20 (conflict-free frags)
    __shared__ float Bs[128 * 20];
    const int tid = threadIdx.x;
    const int lane = tid & 31, w = tid >> 5;
    const int g = lane >> 2, tig = lane & 3;
    const int wm = w & 3, wn = w >> 2;
    const int mBase = blockIdx.y * 128, nBase = blockIdx.x * 128;
    const int wr = wm * 32, wc = wn * 64;

    float acc[2][8][4] = {};

    for (int kt = 0; kt < 32; ++kt) {
        const int k0 = kt * 16;
#pragma unroll
        for (int it = 0; it < 2; ++it) {
            int idx = it * 256 + tid;            // 0..511
            int row = idx >> 2, q = idx & 3;     // row 0..127, q 0..3
            int r = mBase + row; if (r > NDEC - 1) r = NDEC - 1;   // clamp (discarded later)
            float4 av = *(const float4*)(Ahs + (long)r * HH + k0 + q * 4);
            int sb = row * 20 + q * 4;
            As[sb + 0] = to_tf32(av.x); As[sb + 1] = to_tf32(av.y);
            As[sb + 2] = to_tf32(av.z); As[sb + 3] = to_tf32(av.w);
            float4 bv = *(const float4*)(W + (long)(nBase + row) * HH + k0 + q * 4);
            Bs[sb + 0] = to_tf32(bv.x); Bs[sb + 1] = to_tf32(bv.y);
            Bs[sb + 2] = to_tf32(bv.z); Bs[sb + 3] = to_tf32(bv.w);
        }
        __syncthreads();
#pragma unroll
        for (int kb = 0; kb < 2; ++kb) {
            const int kk = kb * 8;
            float a[2][4];
            float bf[8][2];
#pragma unroll
            for (int i = 0; i < 2; ++i) {
                int rr = (wr + i * 16 + g) * 20 + kk + tig;
                a[i][0] = As[rr];
                a[i][1] = As[rr + 8 * 20];
                a[i][2] = As[rr + 4];
                a[i][3] = As[rr + 8 * 20 + 4];
            }
#pragma unroll
            for (int j = 0; j < 8; ++j) {
                int rb = (wc + j * 8 + g) * 20 + kk + tig;
                bf[j][0] = Bs[rb];
                bf[j][1] = Bs[rb + 4];
            }
#pragma unroll
            for (int i = 0; i < 2; ++i)
#pragma unroll
                for (int j = 0; j < 8; ++j)
                    mma_tf32(acc[i][j], a[i], bf[j]);
        }
        __syncthreads();
    }

    // epilogue: row r -> (b = r%64, t = r/64), write out[b][t+1][n..n+1]
#pragma unroll
    for (int i = 0; i < 2; ++i) {
        int rtop = mBase + wr + i * 16 + g;
#pragma unroll
        for (int j = 0; j < 8; ++j) {
            int n = nBase + wc + j * 8 + tig * 2;
            float bb0 = bias[n], bb1 = bias[n + 1];
            if (rtop < NDEC) {
                int b = rtop & 63, t = rtop >> 6;
                float2 v = make_float2(acc[i][j][0] + bb0, acc[i][j][1] + bb1);
                *(float2*)(out + ((long)(b * 32 + t + 1)) * VV + n) = v;
            }
            int rbot = rtop + 8;
            if (rbot < NDEC) {
                int b = rbot & 63, t = rbot >> 6;
                float2 v = make_float2(acc[i][j][2] + bb0, acc[i][j][3] + bb1);
                *(float2*)(out + ((long)(b * 32 + t + 1)) * VV + n) = v;
            }
        }
    }
}

// ---------------------------------------------------------------------------
// kernel_launch: 5 graph nodes total (init, 2 xp GEMMs, recurrence, fc)
// ---------------------------------------------------------------------------
extern "C" void kernel_launch(void* const* d_in, const int* in_sizes, int n_in,
                              void* d_out, int out_size) {
    (void)in_sizes; (void)n_in; (void)out_size;
    const int*   src     = (const int*)  d_in[0];
    const int*   tgt     = (const int*)  d_in[1];
    const float* enc_emb = (const float*)d_in[2];
    const float* dec_emb = (const float*)d_in[3];
    const float* enc_Wih = (const float*)d_in[4];
    const float* enc_Whh = (const float*)d_in[5];
    const float* enc_bih = (const float*)d_in[6];
    const float* enc_bhh = (const float*)d_in[7];
    const float* dec_Wih = (const float*)d_in[8];
    const float* dec_Whh = (const float*)d_in[9];
    const float* dec_bih = (const float*)d_in[10];
    const float* dec_bhh = (const float*)d_in[11];
    const float* fc_W    = (const float*)d_in[12];
    const float* fc_b    = (const float*)d_in[13];
    float* out = (float*)d_out;

    float *xpE, *xpD, *hb, *hs;
    cudaGetSymbolAddress((void**)&xpE, g_xp_enc);
    cudaGetSymbolAddress((void**)&xpD, g_xp_dec);
    cudaGetSymbolAddress((void**)&hb,  g_h);
    cudaGetSymbolAddress((void**)&hs,  g_hseq);

    const int smemBytes = (WS_FLOATS + HS_FLOATS + 256) * sizeof(float);  // ~166 KB
    cudaFuncSetAttribute(lstm_persistent,
                         cudaFuncAttributeMaxDynamicSharedMemorySize, smemBytes);

    // 1) zero out[:,0,:]
    init_kernel<<<(BB * VV + 255) / 256, 256>>>(out);

    // 2) xp = emb[tok] @ Wih^T + (bih + bhh)   [t*64+b][g]
    gemm_fp32<<<dim3(GG / 64, NENC / 64), 256>>>(
        enc_emb, EE, src, SS, enc_Wih, enc_bih, enc_bhh, xpE);
    gemm_fp32<<<dim3(GG / 64, NDEC / 64), 256>>>(
        dec_emb, EE, tgt, 32, dec_Wih, dec_bih, dec_bhh, xpD);

    // 3) fused persistent recurrence: enc 64 + dec 31 steps, 1 launch
    lstm_persistent<<<RGRID, 256, smemBytes>>>(xpE, xpD, enc_Whh, dec_Whh, hb, hs);

    // 4) vocab projection (tf32 tensor cores) -> out[b][t+1][v]
    fc_tf32<<<dim3(VV / 128, (NDEC + 127) / 128), 256>>>(hs, fc_W, fc_b, out);
}

// round 9
// speedup vs baseline: 1.7542x; 1.1956x over previous
#include <cuda_runtime.h>
#include <cuda_fp16.h>
#include <cuda_bf16.h>
#include <cstdint>

// Problem constants
#define BB 64      // batch
#define SS 64      // src length (encoder steps)
#define TD 31      // decoder steps (T-1)
#define EE 256     // embed dim
#define HH 512     // hidden
#define GG 2048    // 4*H gates
#define VV 32000   // vocab
#define NENC (SS*BB)   // 4096 rows
#define NDEC (TD*BB)   // 1984 rows
#define NSTEP (SS+TD)  // 95
#define RGRID 128      // recurrence CTAs (<= SM count -> co-resident)
#define MPAD 2048      // padded hseq rows for fc M tiles

// -------- device scratch (allocation-free rule: __device__ globals) --------
__device__ float g_xp_enc[(size_t)NENC * GG];   // 33.5 MB [t*64+b][g]
__device__ float g_xp_dec[(size_t)NDEC * GG];   // 16.3 MB
__device__ float g_h[2][BB * HH];               // ping-pong hidden state
__device__ float g_hseq[(size_t)NDEC * HH];     // decoder outputs [t*64+b][h]
__device__ __half g_Whf[(size_t)VV * HH];       // 33.5 MB fp16 W
__device__ __half g_Ahf[(size_t)MPAD * HH];     // 2 MB fp16 hseq (padded)

// grid-barrier state: cumulative counters -> replay-safe without reset
__device__ unsigned g_arrive;
__device__ volatile unsigned g_epoch;

// ---------------------------------------------------------------------------
// init: zero out[:,0,:]  (must run every replay; d_out is poisoned)
// ---------------------------------------------------------------------------
__global__ void init_kernel(float* __restrict__ out) {
    long idx = (long)blockIdx.x * 256 + threadIdx.x;
    if (idx < (long)BB * VV) {
        long b = idx / VV, v = idx - b * VV;
        out[b * (32L * VV) + v] = 0.f;           // out[b][0][v]
    }
}

// ---------------------------------------------------------------------------
// fp32 -> fp16 conversion (pads with zeros past nElem)
// ---------------------------------------------------------------------------
__global__ __launch_bounds__(256) void conv_f16(
    const float* __restrict__ src, long nElem,
    __half* __restrict__ dst, long total)
{
    long i = ((long)blockIdx.x * 256 + threadIdx.x) * 8;
    if (i >= total) return;
    __half h[8];
    if (i + 8 <= nElem) {
        float4 v0 = *(const float4*)(src + i);
        float4 v1 = *(const float4*)(src + i + 4);
        h[0] = __float2half_rn(v0.x); h[1] = __float2half_rn(v0.y);
        h[2] = __float2half_rn(v0.z); h[3] = __float2half_rn(v0.w);
        h[4] = __float2half_rn(v1.x); h[5] = __float2half_rn(v1.y);
        h[6] = __float2half_rn(v1.z); h[7] = __float2half_rn(v1.w);
    } else {
#pragma unroll
        for (int j = 0; j < 8; ++j)
            h[j] = __float2half_rn((i + j < nElem) ? src[i + j] : 0.f);
    }
    *(uint4*)(dst + i) = *(const uint4*)h;
}

// ---------------------------------------------------------------------------
// Generic fp32 GEMM for xp: C[r][n] = emb[tok[r]] . Wih[n] + (bih[n]+bhh[n])
// ---------------------------------------------------------------------------
__global__ __launch_bounds__(256) void gemm_fp32(
    const float* __restrict__ A, int lda,
    const int* __restrict__ tok, int tokStride,
    const float* __restrict__ Bw,
    const float* __restrict__ bias0, const float* __restrict__ bias1,
    float* __restrict__ Cout)
{
    __shared__ float As[32 * 65];
    __shared__ float Bs[32 * 65];
    const int tid = threadIdx.x;
    const int nBase = blockIdx.x * 64;
    const int rBase = blockIdx.y * 64;

    const int tm0 = tid >> 4;      // 0..15
    const int tn0 = tid & 15;      // 0..15
    float acc[4][4] = {};

    const int numK = lda >> 5;
    for (int kt = 0; kt < numK; ++kt) {
        const int k0 = kt << 5;
#pragma unroll
        for (int it = 0; it < 2; ++it) {
            int idx = it * 256 + tid;          // 0..511
            int row = idx >> 3, q = idx & 7;   // row 0..63, q 0..7 (float4 slot)
            int r = rBase + row;
            int tokid = tok[(r & 63) * tokStride + (r >> 6)];
            const float* Arow = A + (long)tokid * lda;
            float4 av = *(const float4*)(Arow + k0 + q * 4);
            int sb = (q * 4) * 65 + row;
            As[sb] = av.x; As[sb + 65] = av.y; As[sb + 130] = av.z; As[sb + 195] = av.w;
            const float* Brow = Bw + (long)(nBase + row) * lda;
            float4 bv = *(const float4*)(Brow + k0 + q * 4);
            Bs[sb] = bv.x; Bs[sb + 65] = bv.y; Bs[sb + 130] = bv.z; Bs[sb + 195] = bv.w;
        }
        __syncthreads();
#pragma unroll 8
        for (int k = 0; k < 32; ++k) {
            const float* ar = &As[k * 65];
            const float* br = &Bs[k * 65];
            float a0 = ar[tm0], a1 = ar[tm0 + 16], a2 = ar[tm0 + 32], a3 = ar[tm0 + 48];
            float b0 = br[tn0], b1 = br[tn0 + 16], b2 = br[tn0 + 32], b3 = br[tn0 + 48];
            acc[0][0] += a0 * b0; acc[0][1] += a0 * b1; acc[0][2] += a0 * b2; acc[0][3] += a0 * b3;
            acc[1][0] += a1 * b0; acc[1][1] += a1 * b1; acc[1][2] += a1 * b2; acc[1][3] += a1 * b3;
            acc[2][0] += a2 * b0; acc[2][1] += a2 * b1; acc[2][2] += a2 * b2; acc[2][3] += a2 * b3;
            acc[3][0] += a3 * b0; acc[3][1] += a3 * b1; acc[3][2] += a3 * b2; acc[3][3] += a3 * b3;
        }
        __syncthreads();
    }

#pragma unroll
    for (int i = 0; i < 4; ++i) {
        int r = rBase + tm0 + 16 * i;
#pragma unroll
        for (int j = 0; j < 4; ++j) {
            int n = nBase + tn0 + 16 * j;
            Cout[(long)r * GG + n] = acc[i][j] + bias0[n] + bias1[n];
        }
    }
}

// ---------------------------------------------------------------------------
// Persistent fused LSTM recurrence (unchanged from R5)
// ---------------------------------------------------------------------------
__device__ __forceinline__ float sigf(float x) { return 1.f / (1.f + __expf(-x)); }

__device__ __forceinline__ void grid_sync() {
    __syncthreads();
    if (threadIdx.x == 0) {
        __threadfence();
        unsigned t = atomicAdd(&g_arrive, 1u);
        unsigned target = t / (unsigned)RGRID + 1u;
        if ((t % (unsigned)RGRID) == (unsigned)(RGRID - 1)) {
            g_epoch = target;                     // release
        } else {
            while (g_epoch < target) { }          // tight spin (L2 RTT-paced)
        }
        __threadfence();
    }
    __syncthreads();
}

__device__ __forceinline__ void cp16(float* smem, const float* gmem) {
    unsigned s = (unsigned)__cvta_generic_to_shared(smem);
    asm volatile("cp.async.ca.shared.global [%0], [%1], 16;" :: "r"(s), "l"(gmem));
}
__device__ __forceinline__ void cp16b(uint32_t smem_addr, const void* gmem) {
    asm volatile("cp.async.ca.shared.global [%0], [%1], 16;" :: "r"(smem_addr), "l"(gmem));
}
#define CP_COMMIT() asm volatile("cp.async.commit_group;")
#define CP_WAIT(n)  asm volatile("cp.async.wait_group %0;" :: "n"(n))

#define FMA2(acc, a, b) \
    asm("fma.rn.f32x2 %0, %1, %2, %0;" : "+l"(acc) : "l"(a), "l"(b))

__device__ __forceinline__ float2 unpack2(unsigned long long v) {
    float2 f;
    asm("mov.b64 {%0, %1}, %2;" : "=f"(f.x), "=f"(f.y) : "l"(v));
    return f;
}

#define WS_STRIDE 516
#define WS_FLOATS (16 * WS_STRIDE)
#define HS_FLOATS (64 * WS_STRIDE)

__global__ __launch_bounds__(256, 1) void lstm_persistent(
    const float* __restrict__ xpE, const float* __restrict__ xpD,
    const float* __restrict__ Wenc, const float* __restrict__ Wdec,
    float* __restrict__ hbuf, float* __restrict__ hseq)
{
    extern __shared__ float sm[];
    float* w_s = sm;                    // 16 x 516
    float* h_s = sm + WS_FLOATS;        // 64 x 516
    float* c_s = h_s + HS_FLOATS;       // 256

    const int tid  = threadIdx.x;
    const int lane = tid & 31;
    const int r    = (tid >> 5) * 8 + (lane >> 2);  // 0..63 (batch row)
    const int d    = lane & 3;                      // hidden unit within CTA
    const int J    = blockIdx.x * 4;                // hidden base

    for (int i = tid; i < 16 * 128; i += 256) {
        int c = i >> 7, q = (i & 127) << 2;
        int row = (c >> 2) * 512 + J + (c & 3);
        *(float4*)(w_s + c * WS_STRIDE + q) = *(const float4*)(Wenc + (long)row * HH + q);
    }
    hbuf[(long)r * HH + J + d] = 0.f;
    c_s[tid] = 0.f;
    grid_sync();

    const float* hr  = h_s + r * WS_STRIDE;
    const float* wp0 = w_s + (0  + d) * WS_STRIDE;
    const float* wp1 = w_s + (4  + d) * WS_STRIDE;
    const float* wp2 = w_s + (8  + d) * WS_STRIDE;
    const float* wp3 = w_s + (12 + d) * WS_STRIDE;

    for (int t = 0; t < NSTEP; ++t) {
        const float* xp_t = (t < SS) ? (xpE + (long)t * (BB * GG))
                                     : (xpD + (long)(t - SS) * (BB * GG));
        const long xb = (long)r * GG + J + d;
        float a0 = xp_t[xb];
        float a1 = xp_t[xb + 512];
        float a2 = xp_t[xb + 1024];
        float a3 = xp_t[xb + 1536];

        const float* hin = hbuf + (t & 1) * (BB * HH);
#pragma unroll
        for (int c = 0; c < 2; ++c) {
#pragma unroll
            for (int i = 0; i < 16; ++i) {
                int idx = i * 256 + tid;
                int rr = idx >> 6, q = (idx & 63) << 2;
                cp16(h_s + rr * WS_STRIDE + c * 256 + q,
                     hin + rr * HH + c * 256 + q);
            }
            CP_COMMIT();
        }
        if (t == SS) {
            for (int i = tid; i < 16 * 128; i += 256) {
                int c = i >> 7, q = (i & 127) << 2;
                int row = (c >> 2) * 512 + J + (c & 3);
                *(float4*)(w_s + c * WS_STRIDE + q) = *(const float4*)(Wdec + (long)row * HH + q);
            }
        }

        unsigned long long A0a = 0, A0b = 0, A1a = 0, A1b = 0;
        unsigned long long A2a = 0, A2b = 0, A3a = 0, A3b = 0;

        CP_WAIT(1);
        __syncthreads();
#pragma unroll 4
        for (int k = 0; k < 256; k += 4) {
            ulonglong2 hv = *(const ulonglong2*)(hr + k);
            ulonglong2 w0 = *(const ulonglong2*)(wp0 + k);
            ulonglong2 w1 = *(const ulonglong2*)(wp1 + k);
            ulonglong2 w2 = *(const ulonglong2*)(wp2 + k);
            ulonglong2 w3 = *(const ulonglong2*)(wp3 + k);
            FMA2(A0a, hv.x, w0.x); FMA2(A0b, hv.y, w0.y);
            FMA2(A1a, hv.x, w1.x); FMA2(A1b, hv.y, w1.y);
            FMA2(A2a, hv.x, w2.x); FMA2(A2b, hv.y, w2.y);
            FMA2(A3a, hv.x, w3.x); FMA2(A3b, hv.y, w3.y);
        }
        CP_WAIT(0);
        __syncthreads();
#pragma unroll 4
        for (int k = 256; k < 512; k += 4) {
            ulonglong2 hv = *(const ulonglong2*)(hr + k);
            ulonglong2 w0 = *(const ulonglong2*)(wp0 + k);
            ulonglong2 w1 = *(const ulonglong2*)(wp1 + k);
            ulonglong2 w2 = *(const ulonglong2*)(wp2 + k);
            ulonglong2 w3 = *(const ulonglong2*)(wp3 + k);
            FMA2(A0a, hv.x, w0.x); FMA2(A0b, hv.y, w0.y);
            FMA2(A1a, hv.x, w1.x); FMA2(A1b, hv.y, w1.y);
            FMA2(A2a, hv.x, w2.x); FMA2(A2b, hv.y, w2.y);
            FMA2(A3a, hv.x, w3.x); FMA2(A3b, hv.y, w3.y);
        }

        float2 p, q2;
        p = unpack2(A0a); q2 = unpack2(A0b);
        float gi = a0 + ((p.x + q2.x) + (p.y + q2.y));
        p = unpack2(A1a); q2 = unpack2(A1b);
        float gf = a1 + ((p.x + q2.x) + (p.y + q2.y));
        p = unpack2(A2a); q2 = unpack2(A2b);
        float gg = a2 + ((p.x + q2.x) + (p.y + q2.y));
        p = unpack2(A3a); q2 = unpack2(A3b);
        float go = a3 + ((p.x + q2.x) + (p.y + q2.y));

        float cn = sigf(gf) * c_s[tid] + sigf(gi) * tanhf(gg);
        float hn = sigf(go) * tanhf(cn);
        c_s[tid] = cn;

        float* hout = hbuf + ((t + 1) & 1) * (BB * HH);
        hout[(long)r * HH + J + d] = hn;
        if (t >= SS)
            hseq[(long)(t - SS) * (BB * HH) + (long)r * HH + J + d] = hn;

        grid_sync();
    }
}

// ---------------------------------------------------------------------------
// fc GEMM: fp16 mma.sync m16n8k16 (f32 accum), ldmatrix + XOR swizzle,
// cp.async double buffering.
//   C[m][n] = A[m][:] . W[n][:] + b[n];  out[b][t+1][n], b=m%64, t=m/64.
//   CTA: M=128, N=128, BK=32 fp16. 8 warps = 2(m) x 4(n); warp tile 64x32.
// ---------------------------------------------------------------------------
__device__ __forceinline__ uint32_t smem_u32(const void* p) {
    uint32_t a;
    asm("{ .reg .u64 t; cvta.to.shared.u64 t, %1; cvt.u32.u64 %0, t; }"
        : "=r"(a) : "l"(p));
    return a;
}

#define LDSM4(r, a) \
    asm volatile("ldmatrix.sync.aligned.m8n8.x4.shared.b16 {%0,%1,%2,%3}, [%4];" \
        : "=r"((r)[0]), "=r"((r)[1]), "=r"((r)[2]), "=r"((r)[3]) : "r"(a))

__device__ __forceinline__ void mma_f16(float* d, const uint32_t* a, const uint32_t* b) {
    asm volatile(
        "mma.sync.aligned.m16n8k16.row.col.f32.f16.f16.f32 "
        "{%0,%1,%2,%3}, {%4,%5,%6,%7}, {%8,%9}, {%0,%1,%2,%3};"
        : "+f"(d[0]), "+f"(d[1]), "+f"(d[2]), "+f"(d[3])
        : "r"(a[0]), "r"(a[1]), "r"(a[2]), "r"(a[3]), "r"(b[0]), "r"(b[1]));
}

// swizzled 16B-unit offset for (row, chunk) in a 128x32 fp16 tile (8KB)
__device__ __forceinline__ uint32_t swz16(int row, int chunk) {
    return (uint32_t)(row * 4 + (chunk ^ ((row >> 1) & 3)));
}

__global__ __launch_bounds__(256) void fc_f16(
    const __half* __restrict__ A, const __half* __restrict__ W,
    const float* __restrict__ bias, float* __restrict__ out)
{
    __shared__ __half sA[2][128 * 32];
    __shared__ __half sB[2][128 * 32];
    const int tid = threadIdx.x, wid = tid >> 5, lane = tid & 31;
    const int wm = wid & 1, wn = wid >> 1;
    const int mBase = blockIdx.y * 128;
    const long nBase = (long)blockIdx.x * 128;
    const uint32_t sAb = smem_u32(sA), sBb = smem_u32(sB);

    // per-lane ldmatrix source offsets (bytes within a tile)
    const int matA = lane >> 3;
    const int rowA = wm * 64 + (matA & 1) * 8 + (lane & 7);
    const int swA = (rowA >> 1) & 3;
    const uint32_t aOff0 = (rowA * 4 + (((matA >> 1) + 0) ^ swA)) * 16;
    const uint32_t aOff1 = (rowA * 4 + (((matA >> 1) + 2) ^ swA)) * 16;
    const int rowB = wn * 32 + (matA >> 1) * 8 + (lane & 7);
    const int swB = (rowB >> 1) & 3;
    const uint32_t bOff0 = (rowB * 4 + (((matA & 1) + 0) ^ swB)) * 16;
    const uint32_t bOff1 = (rowB * 4 + (((matA & 1) + 2) ^ swB)) * 16;

    float acc[4][4][4] = {};

    // staging lambda-equivalent (macro-free explicit code, 2 iters x 256 thr)
#define FC_STAGE(buf, kc) do {                                              \
        for (int it = 0; it < 2; ++it) {                                    \
            int idx = it * 256 + tid;          /* 0..511 */                 \
            int row = idx >> 2, ch = idx & 3;                               \
            cp16b(sAb + (buf) * 8192 + swz16(row, ch) * 16,                 \
                  A + (long)(mBase + row) * HH + (kc) * 32 + ch * 8);       \
            cp16b(sBb + (buf) * 8192 + swz16(row, ch) * 16,                 \
                  W + (nBase + row) * (long)HH + (kc) * 32 + ch * 8);       \
        }                                                                   \
        CP_COMMIT();                                                        \
    } while (0)

    FC_STAGE(0, 0);
    for (int kc = 0; kc < 16; ++kc) {
        const int buf = kc & 1;
        __syncthreads();                 // all warps done reading buf^1
        if (kc + 1 < 16) FC_STAGE(buf ^ 1, kc + 1);
        if (kc + 1 < 16) { CP_WAIT(1); } else { CP_WAIT(0); }
        __syncthreads();

        const uint32_t aT = sAb + buf * 8192;
        const uint32_t bT = sBb + buf * 8192;
#pragma unroll
        for (int ks = 0; ks < 2; ++ks) {
            const uint32_t ao = ks ? aOff1 : aOff0;
            const uint32_t bo = ks ? bOff1 : bOff0;
            uint32_t af[4][4];
#pragma unroll
            for (int mi = 0; mi < 4; ++mi)
                LDSM4(af[mi], aT + ao + mi * 1024);
            uint32_t bf[2][4];
            LDSM4(bf[0], bT + bo);
            LDSM4(bf[1], bT + bo + 1024);
#pragma unroll
            for (int mi = 0; mi < 4; ++mi)
#pragma unroll
                for (int ni = 0; ni < 4; ++ni)
                    mma_f16(acc[mi][ni], af[mi], bf[ni >> 1] + (ni & 1) * 2);
        }
    }
#undef FC_STAGE

    // epilogue: add bias, scatter to out[b][t+1][n]
    const int mTop = mBase + wm * 64 + (lane >> 2);
    const long nCol = nBase + wn * 32 + (lane & 3) * 2;
#pragma unroll
    for (int ni = 0; ni < 4; ++ni) {
        long n = nCol + ni * 8;
        float2 bv = *(const float2*)(bias + n);
#pragma unroll
        for (int mi = 0; mi < 4; ++mi) {
            int m0 = mTop + mi * 16;
            if (m0 < NDEC) {
                int b = m0 & 63, t = m0 >> 6;
                float2 v = make_float2(acc[mi][ni][0] + bv.x, acc[mi][ni][1] + bv.y);
                *(float2*)(out + (long)(b * 32 + t + 1) * VV + n) = v;
            }
            int m1 = m0 + 8;
            if (m1 < NDEC) {
                int b = m1 & 63, t = m1 >> 6;
                float2 v = make_float2(acc[mi][ni][2] + bv.x, acc[mi][ni][3] + bv.y);
                *(float2*)(out + (long)(b * 32 + t + 1) * VV + n) = v;
            }
        }
    }
}

// ---------------------------------------------------------------------------
// kernel_launch: init, convW, 2 xp GEMMs, recurrence, convA, fc
// ---------------------------------------------------------------------------
extern "C" void kernel_launch(void* const* d_in, const int* in_sizes, int n_in,
                              void* d_out, int out_size) {
    (void)in_sizes; (void)n_in; (void)out_size;
    const int*   src     = (const int*)  d_in[0];
    const int*   tgt     = (const int*)  d_in[1];
    const float* enc_emb = (const float*)d_in[2];
    const float* dec_emb = (const float*)d_in[3];
    const float* enc_Wih = (const float*)d_in[4];
    const float* enc_Whh = (const float*)d_in[5];
    const float* enc_bih = (const float*)d_in[6];
    const float* enc_bhh = (const float*)d_in[7];
    const float* dec_Wih = (const float*)d_in[8];
    const float* dec_Whh = (const float*)d_in[9];
    const float* dec_bih = (const float*)d_in[10];
    const float* dec_bhh = (const float*)d_in[11];
    const float* fc_W    = (const float*)d_in[12];
    const float* fc_b    = (const float*)d_in[13];
    float* out = (float*)d_out;

    float *xpE, *xpD, *hb, *hs;
    __half *whf, *ahf;
    cudaGetSymbolAddress((void**)&xpE, g_xp_enc);
    cudaGetSymbolAddress((void**)&xpD, g_xp_dec);
    cudaGetSymbolAddress((void**)&hb,  g_h);
    cudaGetSymbolAddress((void**)&hs,  g_hseq);
    cudaGetSymbolAddress((void**)&whf, g_Whf);
    cudaGetSymbolAddress((void**)&ahf, g_Ahf);

    const int recSmem = (WS_FLOATS + HS_FLOATS + 256) * sizeof(float);  // ~166 KB
    cudaFuncSetAttribute(lstm_persistent,
                         cudaFuncAttributeMaxDynamicSharedMemorySize, recSmem);

    // 1) zero out[:,0,:]
    init_kernel<<<(BB * VV + 255) / 256, 256>>>(out);

    // 2) W -> fp16 (independent of everything else)
    {
        long total = (long)VV * HH;
        conv_f16<<<(int)((total / 8 + 255) / 256), 256>>>(fc_W, total, whf, total);
    }

    // 3) xp = emb[tok] @ Wih^T + (bih + bhh)
    gemm_fp32<<<dim3(GG / 64, NENC / 64), 256>>>(
        enc_emb, EE, src, SS, enc_Wih, enc_bih, enc_bhh, xpE);
    gemm_fp32<<<dim3(GG / 64, NDEC / 64), 256>>>(
        dec_emb, EE, tgt, 32, dec_Wih, dec_bih, dec_bhh, xpD);

    // 4) fused persistent recurrence: enc 64 + dec 31 steps, 1 launch
    lstm_persistent<<<RGRID, 256, recSmem>>>(xpE, xpD, enc_Whh, dec_Whh, hb, hs);

    // 5) hseq -> fp16 (padded to MPAD rows with zeros)
    {
        long nElem = (long)NDEC * HH, total = (long)MPAD * HH;
        conv_f16<<<(int)((total / 8 + 255) / 256), 256>>>(hs, nElem, ahf, total);
    }

    // 6) vocab projection on fp16 tensor cores -> out[b][t+1][v]
    fc_f16<<<dim3(VV / 128, MPAD / 128), 256>>>(ahf, whf, fc_b, out);
}

// round 11
// speedup vs baseline: 1.9609x; 1.1178x over previous
#include <cuda_runtime.h>
#include <cuda_fp16.h>
#include <cuda_bf16.h>
#include <cstdint>

// Problem constants
#define BB 64      // batch
#define SS 64      // src length (encoder steps)
#define TD 31      // decoder steps (T-1)
#define EE 256     // embed dim
#define HH 512     // hidden
#define GG 2048    // 4*H gates
#define VV 32000   // vocab
#define NENC (SS*BB)   // 4096 rows
#define NDEC (TD*BB)   // 1984 rows
#define NSTEP (SS+TD)  // 95
#define RGRID 128      // recurrence CTAs (<= SM count -> co-resident)
#define MPAD 2048      // padded hseq rows for fc M tiles

// -------- device scratch (allocation-free rule: __device__ globals) --------
__device__ float g_xp_enc[(size_t)NENC * GG];   // 33.5 MB [t*64+b][g]
__device__ float g_xp_dec[(size_t)NDEC * GG];   // 16.3 MB
__device__ float g_h[2][BB * HH];               // ping-pong hidden state
__device__ float g_hseq[(size_t)NDEC * HH];     // decoder outputs [t*64+b][h]
__device__ __half g_Whf[(size_t)VV * HH];       // 33.5 MB fp16 fc W
__device__ __half g_Ahf[(size_t)MPAD * HH];     // 2 MB fp16 hseq (padded)
__device__ __half g_embE[(size_t)VV * EE];      // 16.4 MB fp16 enc_emb
__device__ __half g_embD[(size_t)VV * EE];      // 16.4 MB fp16 dec_emb
__device__ __half g_wihE[(size_t)GG * EE];      // 1 MB fp16 enc_Wih
__device__ __half g_wihD[(size_t)GG * EE];      // 1 MB fp16 dec_Wih

// grid-barrier state: cumulative counters -> replay-safe without reset
__device__ unsigned g_arrive;
__device__ volatile unsigned g_epoch;

// ---------------------------------------------------------------------------
// init: zero out[:,0,:]  (must run every replay; d_out is poisoned)
// ---------------------------------------------------------------------------
__global__ void init_kernel(float* __restrict__ out) {
    long idx = (long)blockIdx.x * 256 + threadIdx.x;
    if (idx < (long)BB * VV) {
        long b = idx / VV, v = idx - b * VV;
        out[b * (32L * VV) + v] = 0.f;           // out[b][0][v]
    }
}

// ---------------------------------------------------------------------------
// fp32 -> fp16 conversion (pads with zeros past nElem)
// ---------------------------------------------------------------------------
__global__ __launch_bounds__(256) void conv_f16(
    const float* __restrict__ src, long nElem,
    __half* __restrict__ dst, long total)
{
    long i = ((long)blockIdx.x * 256 + threadIdx.x) * 8;
    if (i >= total) return;
    __half h[8];
    if (i + 8 <= nElem) {
        float4 v0 = *(const float4*)(src + i);
        float4 v1 = *(const float4*)(src + i + 4);
        h[0] = __float2half_rn(v0.x); h[1] = __float2half_rn(v0.y);
        h[2] = __float2half_rn(v0.z); h[3] = __float2half_rn(v0.w);
        h[4] = __float2half_rn(v1.x); h[5] = __float2half_rn(v1.y);
        h[6] = __float2half_rn(v1.z); h[7] = __float2half_rn(v1.w);
    } else {
#pragma unroll
        for (int j = 0; j < 8; ++j)
            h[j] = __float2half_rn((i + j < nElem) ? src[i + j] : 0.f);
    }
    *(uint4*)(dst + i) = *(const uint4*)h;
}

// ---------------------------------------------------------------------------
// Shared mma/ldmatrix helpers (fp16, m16n8k16, f32 accum)
// ---------------------------------------------------------------------------
__device__ __forceinline__ uint32_t smem_u32(const void* p) {
    uint32_t a;
    asm("{ .reg .u64 t; cvta.to.shared.u64 t, %1; cvt.u32.u64 %0, t; }"
        : "=r"(a) : "l"(p));
    return a;
}
__device__ __forceinline__ void cp16b(uint32_t smem_addr, const void* gmem) {
    asm volatile("cp.async.ca.shared.global [%0], [%1], 16;" :: "r"(smem_addr), "l"(gmem));
}
#define CP_COMMIT() asm volatile("cp.async.commit_group;")
#define CP_WAIT(n)  asm volatile("cp.async.wait_group %0;" :: "n"(n))

#define LDSM4(r, a) \
    asm volatile("ldmatrix.sync.aligned.m8n8.x4.shared.b16 {%0,%1,%2,%3}, [%4];" \
        : "=r"((r)[0]), "=r"((r)[1]), "=r"((r)[2]), "=r"((r)[3]) : "r"(a))

__device__ __forceinline__ void mma_f16(float* d, const uint32_t* a, const uint32_t* b) {
    asm volatile(
        "mma.sync.aligned.m16n8k16.row.col.f32.f16.f16.f32 "
        "{%0,%1,%2,%3}, {%4,%5,%6,%7}, {%8,%9}, {%0,%1,%2,%3};"
        : "+f"(d[0]), "+f"(d[1]), "+f"(d[2]), "+f"(d[3])
        : "r"(a[0]), "r"(a[1]), "r"(a[2]), "r"(a[3]), "r"(b[0]), "r"(b[1]));
}

// swizzled 16B-unit offset for (row, chunk) in a 128x32 fp16 tile (8KB)
__device__ __forceinline__ uint32_t swz16(int row, int chunk) {
    return (uint32_t)(row * 4 + (chunk ^ ((row >> 1) & 3)));
}

// ---------------------------------------------------------------------------
// fc GEMM: CTA 128x128, 4 warps (2m x 2n), warp tile 64x64, double-buffered.
//   C[m][n] = A[m][:] . W[n][:] + b[n];  out[b][t+1][n], b=m%64, t=m/64.
// ---------------------------------------------------------------------------
__global__ __launch_bounds__(128) void fc_f16(
    const __half* __restrict__ A, const __half* __restrict__ W,
    const float* __restrict__ bias, float* __restrict__ out)
{
    __shared__ __half sA[2][128 * 32];
    __shared__ __half sB[2][128 * 32];
    const int tid = threadIdx.x, wid = tid >> 5, lane = tid & 31;
    const int wm = wid & 1, wn = wid >> 1;
    const int mBase = blockIdx.y * 128;
    const long nBase = (long)blockIdx.x * 128;
    const uint32_t sAb = smem_u32(sA), sBb = smem_u32(sB);

    const int mat = lane >> 3;   // 0..3
    const int rowA = wm * 64 + (mat & 1) * 8 + (lane & 7);
    const int swA = (rowA >> 1) & 3;
    const uint32_t aOff0 = (rowA * 4 + (((mat >> 1) + 0) ^ swA)) * 16;
    const uint32_t aOff1 = (rowA * 4 + (((mat >> 1) + 2) ^ swA)) * 16;
    const int rowB = wn * 64 + (mat >> 1) * 8 + (lane & 7);
    const int swB = (rowB >> 1) & 3;
    const uint32_t bOff0 = (rowB * 4 + (((mat & 1) + 0) ^ swB)) * 16;
    const uint32_t bOff1 = (rowB * 4 + (((mat & 1) + 2) ^ swB)) * 16;

    float acc[4][8][4] = {};

#define FC_STAGE(buf, kc) do {                                              \
        for (int it = 0; it < 4; ++it) {                                    \
            int idx = it * 128 + tid;          /* 0..511 */                 \
            int row = idx >> 2, ch = idx & 3;                               \
            cp16b(sAb + (buf) * 8192 + swz16(row, ch) * 16,                 \
                  A + (long)(mBase + row) * HH + (kc) * 32 + ch * 8);       \
            cp16b(sBb + (buf) * 8192 + swz16(row, ch) * 16,                 \
                  W + (nBase + row) * (long)HH + (kc) * 32 + ch * 8);       \
        }                                                                   \
        CP_COMMIT();                                                        \
    } while (0)

    FC_STAGE(0, 0);
    for (int kc = 0; kc < 16; ++kc) {
        const int buf = kc & 1;
        __syncthreads();                 // all warps done reading buf^1
        if (kc + 1 < 16) FC_STAGE(buf ^ 1, kc + 1);
        if (kc + 1 < 16) { CP_WAIT(1); } else { CP_WAIT(0); }
        __syncthreads();

        const uint32_t aT = sAb + buf * 8192;
        const uint32_t bT = sBb + buf * 8192;
#pragma unroll
        for (int ks = 0; ks < 2; ++ks) {
            const uint32_t ao = ks ? aOff1 : aOff0;
            const uint32_t bo = ks ? bOff1 : bOff0;
            uint32_t af[4][4], bf[4][4];
#pragma unroll
            for (int mi = 0; mi < 4; ++mi)
                LDSM4(af[mi], aT + ao + mi * 1024);
#pragma unroll
            for (int nj = 0; nj < 4; ++nj)
                LDSM4(bf[nj], bT + bo + nj * 1024);
#pragma unroll
            for (int mi = 0; mi < 4; ++mi)
#pragma unroll
                for (int ni = 0; ni < 8; ++ni)
                    mma_f16(acc[mi][ni], af[mi], bf[ni >> 1] + (ni & 1) * 2);
        }
    }
#undef FC_STAGE

    // epilogue: add bias, scatter to out[b][t+1][n]
    const int mTop = mBase + wm * 64 + (lane >> 2);
    const long nCol = nBase + wn * 64 + (lane & 3) * 2;
#pragma unroll
    for (int ni = 0; ni < 8; ++ni) {
        long n = nCol + ni * 8;
        float2 bv = *(const float2*)(bias + n);
#pragma unroll
        for (int mi = 0; mi < 4; ++mi) {
            int m0 = mTop + mi * 16;
            if (m0 < NDEC) {
                int b = m0 & 63, t = m0 >> 6;
                float2 v = make_float2(acc[mi][ni][0] + bv.x, acc[mi][ni][1] + bv.y);
                *(float2*)(out + (long)(b * 32 + t + 1) * VV + n) = v;
            }
            int m1 = m0 + 8;
            if (m1 < NDEC) {
                int b = m1 & 63, t = m1 >> 6;
                float2 v = make_float2(acc[mi][ni][2] + bv.x, acc[mi][ni][3] + bv.y);
                *(float2*)(out + (long)(b * 32 + t + 1) * VV + n) = v;
            }
        }
    }
}

// ---------------------------------------------------------------------------
// xp GEMM (fp16 tensor): xp[r][n] = emb16[tok[r]] . Wih16[n] + bih[n]+bhh[n]
//   Same tiling as fc (CTA 128x128, warp 64x64), K = EE = 256 (8 chunks),
//   A rows gathered via token ids (staged in smem), fp32 output.
// ---------------------------------------------------------------------------
__global__ __launch_bounds__(128) void xp_f16(
    const __half* __restrict__ emb, const int* __restrict__ tok,
    int tokStride, int nRows,
    const __half* __restrict__ Wih,
    const float* __restrict__ bias0, const float* __restrict__ bias1,
    float* __restrict__ xp)
{
    __shared__ __half sA[2][128 * 32];
    __shared__ __half sB[2][128 * 32];
    __shared__ int stok[128];
    const int tid = threadIdx.x, wid = tid >> 5, lane = tid & 31;
    const int wm = wid & 1, wn = wid >> 1;
    const int mBase = blockIdx.y * 128;
    const int nBase = blockIdx.x * 128;
    const uint32_t sAb = smem_u32(sA), sBb = smem_u32(sB);

    if (tid < 128) {
        int r = mBase + tid;
        if (r >= nRows) r = nRows - 1;
        stok[tid] = tok[(r & 63) * tokStride + (r >> 6)];
    }
    __syncthreads();

    const int mat = lane >> 3;
    const int rowA = wm * 64 + (mat & 1) * 8 + (lane & 7);
    const int swA = (rowA >> 1) & 3;
    const uint32_t aOff0 = (rowA * 4 + (((mat >> 1) + 0) ^ swA)) * 16;
    const uint32_t aOff1 = (rowA * 4 + (((mat >> 1) + 2) ^ swA)) * 16;
    const int rowB = wn * 64 + (mat >> 1) * 8 + (lane & 7);
    const int swB = (rowB >> 1) & 3;
    const uint32_t bOff0 = (rowB * 4 + (((mat & 1) + 0) ^ swB)) * 16;
    const uint32_t bOff1 = (rowB * 4 + (((mat & 1) + 2) ^ swB)) * 16;

    float acc[4][8][4] = {};

#define XP_STAGE(buf, kc) do {                                              \
        for (int it = 0; it < 4; ++it) {                                    \
            int idx = it * 128 + tid;                                       \
            int row = idx >> 2, ch = idx & 3;                               \
            cp16b(sAb + (buf) * 8192 + swz16(row, ch) * 16,                 \
                  emb + (long)stok[row] * EE + (kc) * 32 + ch * 8);         \
            cp16b(sBb + (buf) * 8192 + swz16(row, ch) * 16,                 \
                  Wih + (long)(nBase + row) * EE + (kc) * 32 + ch * 8);     \
        }                                                                   \
        CP_COMMIT();                                                        \
    } while (0)

    XP_STAGE(0, 0);
    for (int kc = 0; kc < 8; ++kc) {
        const int buf = kc & 1;
        __syncthreads();
        if (kc + 1 < 8) XP_STAGE(buf ^ 1, kc + 1);
        if (kc + 1 < 8) { CP_WAIT(1); } else { CP_WAIT(0); }
        __syncthreads();

        const uint32_t aT = sAb + buf * 8192;
        const uint32_t bT = sBb + buf * 8192;
#pragma unroll
        for (int ks = 0; ks < 2; ++ks) {
            const uint32_t ao = ks ? aOff1 : aOff0;
            const uint32_t bo = ks ? bOff1 : bOff0;
            uint32_t af[4][4], bf[4][4];
#pragma unroll
            for (int mi = 0; mi < 4; ++mi)
                LDSM4(af[mi], aT + ao + mi * 1024);
#pragma unroll
            for (int nj = 0; nj < 4; ++nj)
                LDSM4(bf[nj], bT + bo + nj * 1024);
#pragma unroll
            for (int mi = 0; mi < 4; ++mi)
#pragma unroll
                for (int ni = 0; ni < 8; ++ni)
                    mma_f16(acc[mi][ni], af[mi], bf[ni >> 1] + (ni & 1) * 2);
        }
    }
#undef XP_STAGE

    const int mTop = mBase + wm * 64 + (lane >> 2);
    const int nCol = nBase + wn * 64 + (lane & 3) * 2;
#pragma unroll
    for (int ni = 0; ni < 8; ++ni) {
        int n = nCol + ni * 8;
        float2 bv = make_float2(bias0[n] + bias1[n], bias0[n + 1] + bias1[n + 1]);
#pragma unroll
        for (int mi = 0; mi < 4; ++mi) {
            int m0 = mTop + mi * 16;
            if (m0 < nRows) {
                float2 v = make_float2(acc[mi][ni][0] + bv.x, acc[mi][ni][1] + bv.y);
                *(float2*)(xp + (long)m0 * GG + n) = v;
            }
            int m1 = m0 + 8;
            if (m1 < nRows) {
                float2 v = make_float2(acc[mi][ni][2] + bv.x, acc[mi][ni][3] + bv.y);
                *(float2*)(xp + (long)m1 * GG + n) = v;
            }
        }
    }
}

// ---------------------------------------------------------------------------
// Persistent fused LSTM recurrence (unchanged from R5)
// ---------------------------------------------------------------------------
__device__ __forceinline__ float sigf(float x) { return 1.f / (1.f + __expf(-x)); }

__device__ __forceinline__ void grid_sync() {
    __syncthreads();
    if (threadIdx.x == 0) {
        __threadfence();
        unsigned t = atomicAdd(&g_arrive, 1u);
        unsigned target = t / (unsigned)RGRID + 1u;
        if ((t % (unsigned)RGRID) == (unsigned)(RGRID - 1)) {
            g_epoch = target;                     // release
        } else {
            while (g_epoch < target) { }          // tight spin (L2 RTT-paced)
        }
        __threadfence();
    }
    __syncthreads();
}

__device__ __forceinline__ void cp16(float* smem, const float* gmem) {
    unsigned s = (unsigned)__cvta_generic_to_shared(smem);
    asm volatile("cp.async.ca.shared.global [%0], [%1], 16;" :: "r"(s), "l"(gmem));
}

#define FMA2(acc, a, b) \
    asm("fma.rn.f32x2 %0, %1, %2, %0;" : "+l"(acc) : "l"(a), "l"(b))

__device__ __forceinline__ float2 unpack2(unsigned long long v) {
    float2 f;
    asm("mov.b64 {%0, %1}, %2;" : "=f"(f.x), "=f"(f.y) : "l"(v));
    return f;
}

#define WS_STRIDE 516
#define WS_FLOATS (16 * WS_STRIDE)
#define HS_FLOATS (64 * WS_STRIDE)

__global__ __launch_bounds__(256, 1) void lstm_persistent(
    const float* __restrict__ xpE, const float* __restrict__ xpD,
    const float* __restrict__ Wenc, const float* __restrict__ Wdec,
    float* __restrict__ hbuf, float* __restrict__ hseq)
{
    extern __shared__ float sm[];
    float* w_s = sm;                    // 16 x 516
    float* h_s = sm + WS_FLOATS;        // 64 x 516
    float* c_s = h_s + HS_FLOATS;       // 256

    const int tid  = threadIdx.x;
    const int lane = tid & 31;
    const int r    = (tid >> 5) * 8 + (lane >> 2);  // 0..63 (batch row)
    const int d    = lane & 3;                      // hidden unit within CTA
    const int J    = blockIdx.x * 4;                // hidden base

    for (int i = tid; i < 16 * 128; i += 256) {
        int c = i >> 7, q = (i & 127) << 2;
        int row = (c >> 2) * 512 + J + (c & 3);
        *(float4*)(w_s + c * WS_STRIDE + q) = *(const float4*)(Wenc + (long)row * HH + q);
    }
    hbuf[(long)r * HH + J + d] = 0.f;
    c_s[tid] = 0.f;
    grid_sync();

    const float* hr  = h_s + r * WS_STRIDE;
    const float* wp0 = w_s + (0  + d) * WS_STRIDE;
    const float* wp1 = w_s + (4  + d) * WS_STRIDE;
    const float* wp2 = w_s + (8  + d) * WS_STRIDE;
    const float* wp3 = w_s + (12 + d) * WS_STRIDE;

    for (int t = 0; t < NSTEP; ++t) {
        const float* xp_t = (t < SS) ? (xpE + (long)t * (BB * GG))
                                     : (xpD + (long)(t - SS) * (BB * GG));
        const long xb = (long)r * GG + J + d;
        float a0 = xp_t[xb];
        float a1 = xp_t[xb + 512];
        float a2 = xp_t[xb + 1024];
        float a3 = xp_t[xb + 1536];

        const float* hin = hbuf + (t & 1) * (BB * HH);
#pragma unroll
        for (int c = 0; c < 2; ++c) {
#pragma unroll
            for (int i = 0; i < 16; ++i) {
                int idx = i * 256 + tid;
                int rr = idx >> 6, q = (idx & 63) << 2;
                cp16(h_s + rr * WS_STRIDE + c * 256 + q,
                     hin + rr * HH + c * 256 + q);
            }
            CP_COMMIT();
        }
        if (t == SS) {
            for (int i = tid; i < 16 * 128; i += 256) {
                int c = i >> 7, q = (i & 127) << 2;
                int row = (c >> 2) * 512 + J + (c & 3);
                *(float4*)(w_s + c * WS_STRIDE + q) = *(const float4*)(Wdec + (long)row * HH + q);
            }
        }

        unsigned long long A0a = 0, A0b = 0, A1a = 0, A1b = 0;
        unsigned long long A2a = 0, A2b = 0, A3a = 0, A3b = 0;

        CP_WAIT(1);
        __syncthreads();
#pragma unroll 4
        for (int k = 0; k < 256; k += 4) {
            ulonglong2 hv = *(const ulonglong2*)(hr + k);
            ulonglong2 w0 = *(const ulonglong2*)(wp0 + k);
            ulonglong2 w1 = *(const ulonglong2*)(wp1 + k);
            ulonglong2 w2 = *(const ulonglong2*)(wp2 + k);
            ulonglong2 w3 = *(const ulonglong2*)(wp3 + k);
            FMA2(A0a, hv.x, w0.x); FMA2(A0b, hv.y, w0.y);
            FMA2(A1a, hv.x, w1.x); FMA2(A1b, hv.y, w1.y);
            FMA2(A2a, hv.x, w2.x); FMA2(A2b, hv.y, w2.y);
            FMA2(A3a, hv.x, w3.x); FMA2(A3b, hv.y, w3.y);
        }
        CP_WAIT(0);
        __syncthreads();
#pragma unroll 4
        for (int k = 256; k < 512; k += 4) {
            ulonglong2 hv = *(const ulonglong2*)(hr + k);
            ulonglong2 w0 = *(const ulonglong2*)(wp0 + k);
            ulonglong2 w1 = *(const ulonglong2*)(wp1 + k);
            ulonglong2 w2 = *(const ulonglong2*)(wp2 + k);
            ulonglong2 w3 = *(const ulonglong2*)(wp3 + k);
            FMA2(A0a, hv.x, w0.x); FMA2(A0b, hv.y, w0.y);
            FMA2(A1a, hv.x, w1.x); FMA2(A1b, hv.y, w1.y);
            FMA2(A2a, hv.x, w2.x); FMA2(A2b, hv.y, w2.y);
            FMA2(A3a, hv.x, w3.x); FMA2(A3b, hv.y, w3.y);
        }

        float2 p, q2;
        p = unpack2(A0a); q2 = unpack2(A0b);
        float gi = a0 + ((p.x + q2.x) + (p.y + q2.y));
        p = unpack2(A1a); q2 = unpack2(A1b);
        float gf = a1 + ((p.x + q2.x) + (p.y + q2.y));
        p = unpack2(A2a); q2 = unpack2(A2b);
        float gg = a2 + ((p.x + q2.x) + (p.y + q2.y));
        p = unpack2(A3a); q2 = unpack2(A3b);
        float go = a3 + ((p.x + q2.x) + (p.y + q2.y));

        float cn = sigf(gf) * c_s[tid] + sigf(gi) * tanhf(gg);
        float hn = sigf(go) * tanhf(cn);
        c_s[tid] = cn;

        float* hout = hbuf + ((t + 1) & 1) * (BB * HH);
        hout[(long)r * HH + J + d] = hn;
        if (t >= SS)
            hseq[(long)(t - SS) * (BB * HH) + (long)r * HH + J + d] = hn;

        grid_sync();
    }
}

// ---------------------------------------------------------------------------
// kernel_launch
// ---------------------------------------------------------------------------
extern "C" void kernel_launch(void* const* d_in, const int* in_sizes, int n_in,
                              void* d_out, int out_size) {
    (void)in_sizes; (void)n_in; (void)out_size;
    const int*   src     = (const int*)  d_in[0];
    const int*   tgt     = (const int*)  d_in[1];
    const float* enc_emb = (const float*)d_in[2];
    const float* dec_emb = (const float*)d_in[3];
    const float* enc_Wih = (const float*)d_in[4];
    const float* enc_Whh = (const float*)d_in[5];
    const float* enc_bih = (const float*)d_in[6];
    const float* enc_bhh = (const float*)d_in[7];
    const float* dec_Wih = (const float*)d_in[8];
    const float* dec_Whh = (const float*)d_in[9];
    const float* dec_bih = (const float*)d_in[10];
    const float* dec_bhh = (const float*)d_in[11];
    const float* fc_W    = (const float*)d_in[12];
    const float* fc_b    = (const float*)d_in[13];
    float* out = (float*)d_out;

    float *xpE, *xpD, *hb, *hs;
    __half *whf, *ahf, *embE, *embD, *wihE, *wihD;
    cudaGetSymbolAddress((void**)&xpE, g_xp_enc);
    cudaGetSymbolAddress((void**)&xpD, g_xp_dec);
    cudaGetSymbolAddress((void**)&hb,  g_h);
    cudaGetSymbolAddress((void**)&hs,  g_hseq);
    cudaGetSymbolAddress((void**)&whf, g_Whf);
    cudaGetSymbolAddress((void**)&ahf, g_Ahf);
    cudaGetSymbolAddress((void**)&embE, g_embE);
    cudaGetSymbolAddress((void**)&embD, g_embD);
    cudaGetSymbolAddress((void**)&wihE, g_wihE);
    cudaGetSymbolAddress((void**)&wihD, g_wihD);

    const int recSmem = (WS_FLOATS + HS_FLOATS + 256) * sizeof(float);  // ~166 KB
    cudaFuncSetAttribute(lstm_persistent,
                         cudaFuncAttributeMaxDynamicSharedMemorySize, recSmem);

    // 1) zero out[:,0,:]
    init_kernel<<<(BB * VV + 255) / 256, 256>>>(out);

    // 2) fp16 conversions (tables + weights)
    {
        long n;
        n = (long)VV * EE;
        conv_f16<<<(int)((n / 8 + 255) / 256), 256>>>(enc_emb, n, embE, n);
        conv_f16<<<(int)((n / 8 + 255) / 256), 256>>>(dec_emb, n, embD, n);
        n = (long)GG * EE;
        conv_f16<<<(int)((n / 8 + 255) / 256), 256>>>(enc_Wih, n, wihE, n);
        conv_f16<<<(int)((n / 8 + 255) / 256), 256>>>(dec_Wih, n, wihD, n);
        n = (long)VV * HH;
        conv_f16<<<(int)((n / 8 + 255) / 256), 256>>>(fc_W, n, whf, n);
    }

    // 3) xp = emb[tok] @ Wih^T + (bih + bhh)  on fp16 tensor cores
    xp_f16<<<dim3(GG / 128, NENC / 128), 128>>>(
        embE, src, SS, NENC, wihE, enc_bih, enc_bhh, xpE);
    xp_f16<<<dim3(GG / 128, (NDEC + 127) / 128), 128>>>(
        embD, tgt, 32, NDEC, wihD, dec_bih, dec_bhh, xpD);

    // 4) fused persistent recurrence: enc 64 + dec 31 steps, 1 launch
    lstm_persistent<<<RGRID, 256, recSmem>>>(xpE, xpD, enc_Whh, dec_Whh, hb, hs);

    // 5) hseq -> fp16 (padded to MPAD rows with zeros)
    {
        long nElem = (long)NDEC * HH, total = (long)MPAD * HH;
        conv_f16<<<(int)((total / 8 + 255) / 256), 256>>>(hs, nElem, ahf, total);
    }

    // 6) vocab projection on fp16 tensor cores -> out[b][t+1][v]
    fc_f16<<<dim3(VV / 128, MPAD / 128), 128>>>(ahf, whf, fc_b, out);
}

// round 12
// speedup vs baseline: 1.9797x; 1.0096x over previous
#include <cuda_runtime.h>
#include <cuda_fp16.h>
#include <cuda_bf16.h>
#include <cstdint>

// Problem constants
#define BB 64      // batch
#define SS 64      // src length (encoder steps)
#define TD 31      // decoder steps (T-1)
#define EE 256     // embed dim
#define HH 512     // hidden
#define GG 2048    // 4*H gates
#define VV 32000   // vocab
#define NENC (SS*BB)   // 4096 rows
#define NDEC (TD*BB)   // 1984 rows
#define NSTEP (SS+TD)  // 95
#define RGRID 128      // recurrence CTAs (<= SM count -> co-resident)
#define MPAD 2048      // padded hseq rows for fc M tiles

// -------- device scratch (allocation-free rule: __device__ globals) --------
__device__ float g_xp_enc[(size_t)NENC * GG];   // 33.5 MB [t*64+b][g]
__device__ float g_xp_dec[(size_t)NDEC * GG];   // 16.3 MB
__device__ float g_h[2][BB * HH];               // ping-pong hidden state
__device__ float g_hseq[(size_t)NDEC * HH];     // decoder outputs [t*64+b][h]
__device__ __half g_Whf[(size_t)VV * HH];       // 33.5 MB fp16 fc W
__device__ __half g_Ahf[(size_t)MPAD * HH];     // 2 MB fp16 hseq (padded)
__device__ __half g_embE[(size_t)VV * EE];      // 16.4 MB fp16 enc_emb
__device__ __half g_embD[(size_t)VV * EE];      // 16.4 MB fp16 dec_emb
__device__ __half g_wihE[(size_t)GG * EE];      // 1 MB fp16 enc_Wih
__device__ __half g_wihD[(size_t)GG * EE];      // 1 MB fp16 dec_Wih

// grid-barrier state: cumulative counters -> replay-safe without reset
__device__ unsigned g_arrive;
__device__ unsigned g_epoch;

// ---------------------------------------------------------------------------
// init: zero out[:,0,:]  (vectorized; VV % 4 == 0 so float4 stays in-row)
// ---------------------------------------------------------------------------
__global__ void init_kernel(float* __restrict__ out) {
    long idx = ((long)blockIdx.x * 256 + threadIdx.x) * 4;
    if (idx < (long)BB * VV) {
        long b = idx / VV, v = idx - b * VV;
        *(float4*)(out + b * (32L * VV) + v) = make_float4(0.f, 0.f, 0.f, 0.f);
    }
}

// ---------------------------------------------------------------------------
// fp32 -> fp16 conversion (pads with zeros past nElem)
// ---------------------------------------------------------------------------
__global__ __launch_bounds__(256) void conv_f16(
    const float* __restrict__ src, long nElem,
    __half* __restrict__ dst, long total)
{
    long i = ((long)blockIdx.x * 256 + threadIdx.x) * 8;
    if (i >= total) return;
    __half h[8];
    if (i + 8 <= nElem) {
        float4 v0 = *(const float4*)(src + i);
        float4 v1 = *(const float4*)(src + i + 4);
        h[0] = __float2half_rn(v0.x); h[1] = __float2half_rn(v0.y);
        h[2] = __float2half_rn(v0.z); h[3] = __float2half_rn(v0.w);
        h[4] = __float2half_rn(v1.x); h[5] = __float2half_rn(v1.y);
        h[6] = __float2half_rn(v1.z); h[7] = __float2half_rn(v1.w);
    } else {
#pragma unroll
        for (int j = 0; j < 8; ++j)
            h[j] = __float2half_rn((i + j < nElem) ? src[i + j] : 0.f);
    }
    *(uint4*)(dst + i) = *(const uint4*)h;
}

// ---------------------------------------------------------------------------
// Shared mma/ldmatrix helpers (fp16, m16n8k16, f32 accum)
// ---------------------------------------------------------------------------
__device__ __forceinline__ uint32_t smem_u32(const void* p) {
    uint32_t a;
    asm("{ .reg .u64 t; cvta.to.shared.u64 t, %1; cvt.u32.u64 %0, t; }"
        : "=r"(a) : "l"(p));
    return a;
}
__device__ __forceinline__ void cp16b(uint32_t smem_addr, const void* gmem) {
    asm volatile("cp.async.ca.shared.global [%0], [%1], 16;" :: "r"(smem_addr), "l"(gmem));
}
#define CP_COMMIT() asm volatile("cp.async.commit_group;")
#define CP_WAIT(n)  asm volatile("cp.async.wait_group %0;" :: "n"(n))

#define LDSM4(r, a) \
    asm volatile("ldmatrix.sync.aligned.m8n8.x4.shared.b16 {%0,%1,%2,%3}, [%4];" \
        : "=r"((r)[0]), "=r"((r)[1]), "=r"((r)[2]), "=r"((r)[3]) : "r"(a))

__device__ __forceinline__ void mma_f16(float* d, const uint32_t* a, const uint32_t* b) {
    asm volatile(
        "mma.sync.aligned.m16n8k16.row.col.f32.f16.f16.f32 "
        "{%0,%1,%2,%3}, {%4,%5,%6,%7}, {%8,%9}, {%0,%1,%2,%3};"
        : "+f"(d[0]), "+f"(d[1]), "+f"(d[2]), "+f"(d[3])
        : "r"(a[0]), "r"(a[1]), "r"(a[2]), "r"(a[3]), "r"(b[0]), "r"(b[1]));
}

// swizzled 16B-unit offset for (row, chunk) in a 128x32 fp16 tile (64B rows)
__device__ __forceinline__ uint32_t swz16(int row, int chunk) {
    return (uint32_t)(row * 4 + (chunk ^ ((row >> 1) & 3)));
}

// ---------------------------------------------------------------------------
// fc GEMM: CTA 128x128, 8 warps (4m x 2n), warp tile 32x64.
//   K-chunk 64 (8 chunks), 3-stage cp.async ring, ONE syncthreads per chunk.
//   128B rows in smem, swizzle<3,3,3>: unit16 = row*8 + (ch ^ (row&7)).
//   C[m][n] = A[m][:] . W[n][:] + b[n];  out[b][t+1][n], b=m%64, t=m/64.
// ---------------------------------------------------------------------------
#define FC_STG 32768             // bytes per stage (A 16KB + B 16KB)

__global__ __launch_bounds__(256, 2) void fc_f16(
    const __half* __restrict__ A, const __half* __restrict__ W,
    const float* __restrict__ bias, float* __restrict__ out)
{
    extern __shared__ __half fsm[];
    const int tid = threadIdx.x, wid = tid >> 5, lane = tid & 31;
    const int wm = wid & 3, wn = wid >> 2;
    const int mBase = blockIdx.y * 128;
    const long nBase = (long)blockIdx.x * 128;
    const uint32_t sb = smem_u32(fsm);

    const int mat = lane >> 3;           // 0..3
    const int abit = mat >> 1, bbit = mat & 1;
    // A fragment rows (2 m16 tiles), B fragment rows (4 n16 tiles)
    int rA[2], rB[4];
#pragma unroll
    for (int mi = 0; mi < 2; ++mi) rA[mi] = wm * 32 + mi * 16 + (mat & 1) * 8 + (lane & 7);
#pragma unroll
    for (int nj = 0; nj < 4; ++nj) rB[nj] = wn * 64 + nj * 16 + (mat >> 1) * 8 + (lane & 7);

    float acc[2][8][4] = {};

#define FC_STAGE(s, kc) do {                                                \
        uint32_t base = sb + (s) * FC_STG;                                  \
        for (int it = 0; it < 4; ++it) {                                    \
            int idx = it * 256 + tid;          /* 0..1023 */                \
            int row = idx >> 3, ch = idx & 7;                               \
            uint32_t sw = (uint32_t)(row * 8 + (ch ^ (row & 7))) * 16;      \
            cp16b(base + sw,                                                \
                  A + (long)(mBase + row) * HH + (kc) * 64 + ch * 8);       \
            cp16b(base + 16384 + sw,                                        \
                  W + (nBase + row) * (long)HH + (kc) * 64 + ch * 8);       \
        }                                                                   \
        CP_COMMIT();                                                        \
    } while (0)

    FC_STAGE(0, 0);
    FC_STAGE(1, 1);
    int sCur = 0;
    for (int kc = 0; kc < 8; ++kc) {
        if (kc < 7) { CP_WAIT(1); } else { CP_WAIT(0); }
        __syncthreads();                  // data of chunk kc visible; buf (kc+2)%3 free
        if (kc + 2 < 8) FC_STAGE((sCur + 2 == 3) ? ((sCur + 2) - 3) : (sCur + 2 > 2 ? sCur - 1 : sCur + 2), kc + 2);
        const uint32_t aT = sb + sCur * FC_STG;
        const uint32_t bT = aT + 16384;
#pragma unroll
        for (int ks = 0; ks < 4; ++ks) {
            uint32_t af[2][4], bf[4][4];
#pragma unroll
            for (int mi = 0; mi < 2; ++mi) {
                uint32_t c = (uint32_t)((2 * ks + abit) ^ (rA[mi] & 7));
                LDSM4(af[mi], aT + (uint32_t)(rA[mi] * 8 + c) * 16);
            }
#pragma unroll
            for (int nj = 0; nj < 4; ++nj) {
                uint32_t c = (uint32_t)((2 * ks + bbit) ^ (rB[nj] & 7));
                LDSM4(bf[nj], bT + (uint32_t)(rB[nj] * 8 + c) * 16);
            }
#pragma unroll
            for (int mi = 0; mi < 2; ++mi)
#pragma unroll
                for (int ni = 0; ni < 8; ++ni)
                    mma_f16(acc[mi][ni], af[mi], bf[ni >> 1] + (ni & 1) * 2);
        }
        sCur = (sCur == 2) ? 0 : sCur + 1;
    }
#undef FC_STAGE

    // epilogue: add bias, scatter to out[b][t+1][n]
    const int mTop = mBase + wm * 32 + (lane >> 2);
    const long nCol = nBase + wn * 64 + (lane & 3) * 2;
#pragma unroll
    for (int ni = 0; ni < 8; ++ni) {
        long n = nCol + ni * 8;
        float2 bv = *(const float2*)(bias + n);
#pragma unroll
        for (int mi = 0; mi < 2; ++mi) {
            int m0 = mTop + mi * 16;
            if (m0 < NDEC) {
                int b = m0 & 63, t = m0 >> 6;
                float2 v = make_float2(acc[mi][ni][0] + bv.x, acc[mi][ni][1] + bv.y);
                *(float2*)(out + (long)(b * 32 + t + 1) * VV + n) = v;
            }
            int m1 = m0 + 8;
            if (m1 < NDEC) {
                int b = m1 & 63, t = m1 >> 6;
                float2 v = make_float2(acc[mi][ni][2] + bv.x, acc[mi][ni][3] + bv.y);
                *(float2*)(out + (long)(b * 32 + t + 1) * VV + n) = v;
            }
        }
    }
}

// ---------------------------------------------------------------------------
// xp GEMM (fp16 tensor): xp[r][n] = emb16[tok[r]] . Wih16[n] + bih[n]+bhh[n]
//   (unchanged from R11: CTA 128x128, warp 64x64, K=256, double buffer)
// ---------------------------------------------------------------------------
__global__ __launch_bounds__(128) void xp_f16(
    const __half* __restrict__ emb, const int* __restrict__ tok,
    int tokStride, int nRows,
    const __half* __restrict__ Wih,
    const float* __restrict__ bias0, const float* __restrict__ bias1,
    float* __restrict__ xp)
{
    __shared__ __half sA[2][128 * 32];
    __shared__ __half sB[2][128 * 32];
    __shared__ int stok[128];
    const int tid = threadIdx.x, wid = tid >> 5, lane = tid & 31;
    const int wm = wid & 1, wn = wid >> 1;
    const int mBase = blockIdx.y * 128;
    const int nBase = blockIdx.x * 128;
    const uint32_t sAb = smem_u32(sA), sBb = smem_u32(sB);

    if (tid < 128) {
        int r = mBase + tid;
        if (r >= nRows) r = nRows - 1;
        stok[tid] = tok[(r & 63) * tokStride + (r >> 6)];
    }
    __syncthreads();

    const int mat = lane >> 3;
    const int rowA = wm * 64 + (mat & 1) * 8 + (lane & 7);
    const int swA = (rowA >> 1) & 3;
    const uint32_t aOff0 = (rowA * 4 + (((mat >> 1) + 0) ^ swA)) * 16;
    const uint32_t aOff1 = (rowA * 4 + (((mat >> 1) + 2) ^ swA)) * 16;
    const int rowB = wn * 64 + (mat >> 1) * 8 + (lane & 7);
    const int swB = (rowB >> 1) & 3;
    const uint32_t bOff0 = (rowB * 4 + (((mat & 1) + 0) ^ swB)) * 16;
    const uint32_t bOff1 = (rowB * 4 + (((mat & 1) + 2) ^ swB)) * 16;

    float acc[4][8][4] = {};

#define XP_STAGE(buf, kc) do {                                              \
        for (int it = 0; it < 4; ++it) {                                    \
            int idx = it * 128 + tid;                                       \
            int row = idx >> 2, ch = idx & 3;                               \
            cp16b(sAb + (buf) * 8192 + swz16(row, ch) * 16,                 \
                  emb + (long)stok[row] * EE + (kc) * 32 + ch * 8);         \
            cp16b(sBb + (buf) * 8192 + swz16(row, ch) * 16,                 \
                  Wih + (long)(nBase + row) * EE + (kc) * 32 + ch * 8);     \
        }                                                                   \
        CP_COMMIT();                                                        \
    } while (0)

    XP_STAGE(0, 0);
    for (int kc = 0; kc < 8; ++kc) {
        const int buf = kc & 1;
        __syncthreads();
        if (kc + 1 < 8) XP_STAGE(buf ^ 1, kc + 1);
        if (kc + 1 < 8) { CP_WAIT(1); } else { CP_WAIT(0); }
        __syncthreads();

        const uint32_t aT = sAb + buf * 8192;
        const uint32_t bT = sBb + buf * 8192;
#pragma unroll
        for (int ks = 0; ks < 2; ++ks) {
            const uint32_t ao = ks ? aOff1 : aOff0;
            const uint32_t bo = ks ? bOff1 : bOff0;
            uint32_t af[4][4], bf[4][4];
#pragma unroll
            for (int mi = 0; mi < 4; ++mi)
                LDSM4(af[mi], aT + ao + mi * 1024);
#pragma unroll
            for (int nj = 0; nj < 4; ++nj)
                LDSM4(bf[nj], bT + bo + nj * 1024);
#pragma unroll
            for (int mi = 0; mi < 4; ++mi)
#pragma unroll
                for (int ni = 0; ni < 8; ++ni)
                    mma_f16(acc[mi][ni], af[mi], bf[ni >> 1] + (ni & 1) * 2);
        }
    }
#undef XP_STAGE

    const int mTop = mBase + wm * 64 + (lane >> 2);
    const int nCol = nBase + wn * 64 + (lane & 3) * 2;
#pragma unroll
    for (int ni = 0; ni < 8; ++ni) {
        int n = nCol + ni * 8;
        float2 bv = make_float2(bias0[n] + bias1[n], bias0[n + 1] + bias1[n + 1]);
#pragma unroll
        for (int mi = 0; mi < 4; ++mi) {
            int m0 = mTop + mi * 16;
            if (m0 < nRows) {
                float2 v = make_float2(acc[mi][ni][0] + bv.x, acc[mi][ni][1] + bv.y);
                *(float2*)(xp + (long)m0 * GG + n) = v;
            }
            int m1 = m0 + 8;
            if (m1 < nRows) {
                float2 v = make_float2(acc[mi][ni][2] + bv.x, acc[mi][ni][3] + bv.y);
                *(float2*)(xp + (long)m1 * GG + n) = v;
            }
        }
    }
}

// ---------------------------------------------------------------------------
// Persistent fused LSTM recurrence.
//   R12: acq_rel barrier (no MEMBAR.GPU), xp prefetch before grid_sync.
// ---------------------------------------------------------------------------
__device__ __forceinline__ float sigf(float x) { return 1.f / (1.f + __expf(-x)); }

__device__ __forceinline__ void grid_sync() {
    __syncthreads();
    if (threadIdx.x == 0) {
        unsigned t;
        asm volatile("atom.add.acq_rel.gpu.u32 %0, [%1], 1;"
                     : "=r"(t) : "l"(&g_arrive) : "memory");
        unsigned target = t / (unsigned)RGRID + 1u;
        if ((t % (unsigned)RGRID) == (unsigned)(RGRID - 1)) {
            asm volatile("st.release.gpu.u32 [%0], %1;"
                         :: "l"(&g_epoch), "r"(target) : "memory");
        } else {
            unsigned e;
            do {
                asm volatile("ld.acquire.gpu.u32 %0, [%1];"
                             : "=r"(e) : "l"(&g_epoch) : "memory");
            } while (e < target);
        }
    }
    __syncthreads();
}

__device__ __forceinline__ void cp16(float* smem, const float* gmem) {
    unsigned s = (unsigned)__cvta_generic_to_shared(smem);
    asm volatile("cp.async.ca.shared.global [%0], [%1], 16;" :: "r"(s), "l"(gmem));
}

#define FMA2(acc, a, b) \
    asm("fma.rn.f32x2 %0, %1, %2, %0;" : "+l"(acc) : "l"(a), "l"(b))

__device__ __forceinline__ float2 unpack2(unsigned long long v) {
    float2 f;
    asm("mov.b64 {%0, %1}, %2;" : "=f"(f.x), "=f"(f.y) : "l"(v));
    return f;
}

#define WS_STRIDE 516
#define WS_FLOATS (16 * WS_STRIDE)
#define HS_FLOATS (64 * WS_STRIDE)

__global__ __launch_bounds__(256, 1) void lstm_persistent(
    const float* __restrict__ xpE, const float* __restrict__ xpD,
    const float* __restrict__ Wenc, const float* __restrict__ Wdec,
    float* __restrict__ hbuf, float* __restrict__ hseq)
{
    extern __shared__ float sm[];
    float* w_s = sm;                    // 16 x 516
    float* h_s = sm + WS_FLOATS;        // 64 x 516
    float* c_s = h_s + HS_FLOATS;       // 256

    const int tid  = threadIdx.x;
    const int lane = tid & 31;
    const int r    = (tid >> 5) * 8 + (lane >> 2);  // 0..63 (batch row)
    const int d    = lane & 3;                      // hidden unit within CTA
    const int J    = blockIdx.x * 4;                // hidden base

    for (int i = tid; i < 16 * 128; i += 256) {
        int c = i >> 7, q = (i & 127) << 2;
        int row = (c >> 2) * 512 + J + (c & 3);
        *(float4*)(w_s + c * WS_STRIDE + q) = *(const float4*)(Wenc + (long)row * HH + q);
    }
    hbuf[(long)r * HH + J + d] = 0.f;
    c_s[tid] = 0.f;
    grid_sync();

    const float* hr  = h_s + r * WS_STRIDE;
    const float* wp0 = w_s + (0  + d) * WS_STRIDE;
    const float* wp1 = w_s + (4  + d) * WS_STRIDE;
    const float* wp2 = w_s + (8  + d) * WS_STRIDE;
    const float* wp3 = w_s + (12 + d) * WS_STRIDE;

    const long xb = (long)r * GG + J + d;
    // prefetch xp for t=0
    float a0 = xpE[xb], a1 = xpE[xb + 512], a2 = xpE[xb + 1024], a3 = xpE[xb + 1536];

    for (int t = 0; t < NSTEP; ++t) {
        // stage h[t] into SMEM in two 256-col chunks via cp.async
        const float* hin = hbuf + (t & 1) * (BB * HH);
#pragma unroll
        for (int c = 0; c < 2; ++c) {
#pragma unroll
            for (int i = 0; i < 16; ++i) {
                int idx = i * 256 + tid;
                int rr = idx >> 6, q = (idx & 63) << 2;
                cp16(h_s + rr * WS_STRIDE + c * 256 + q,
                     hin + rr * HH + c * 256 + q);
            }
            CP_COMMIT();
        }
        if (t == SS) {
            for (int i = tid; i < 16 * 128; i += 256) {
                int c = i >> 7, q = (i & 127) << 2;
                int row = (c >> 2) * 512 + J + (c & 3);
                *(float4*)(w_s + c * WS_STRIDE + q) = *(const float4*)(Wdec + (long)row * HH + q);
            }
        }

        unsigned long long A0a = 0, A0b = 0, A1a = 0, A1b = 0;
        unsigned long long A2a = 0, A2b = 0, A3a = 0, A3b = 0;

        CP_WAIT(1);
        __syncthreads();
#pragma unroll 4
        for (int k = 0; k < 256; k += 4) {
            ulonglong2 hv = *(const ulonglong2*)(hr + k);
            ulonglong2 w0 = *(const ulonglong2*)(wp0 + k);
            ulonglong2 w1 = *(const ulonglong2*)(wp1 + k);
            ulonglong2 w2 = *(const ulonglong2*)(wp2 + k);
            ulonglong2 w3 = *(const ulonglong2*)(wp3 + k);
            FMA2(A0a, hv.x, w0.x); FMA2(A0b, hv.y, w0.y);
            FMA2(A1a, hv.x, w1.x); FMA2(A1b, hv.y, w1.y);
            FMA2(A2a, hv.x, w2.x); FMA2(A2b, hv.y, w2.y);
            FMA2(A3a, hv.x, w3.x); FMA2(A3b, hv.y, w3.y);
        }
        CP_WAIT(0);
        __syncthreads();
#pragma unroll 4
        for (int k = 256; k < 512; k += 4) {
            ulonglong2 hv = *(const ulonglong2*)(hr + k);
            ulonglong2 w0 = *(const ulonglong2*)(wp0 + k);
            ulonglong2 w1 = *(const ulonglong2*)(wp1 + k);
            ulonglong2 w2 = *(const ulonglong2*)(wp2 + k);
            ulonglong2 w3 = *(const ulonglong2*)(wp3 + k);
            FMA2(A0a, hv.x, w0.x); FMA2(A0b, hv.y, w0.y);
            FMA2(A1a, hv.x, w1.x); FMA2(A1b, hv.y, w1.y);
            FMA2(A2a, hv.x, w2.x); FMA2(A2b, hv.y, w2.y);
            FMA2(A3a, hv.x, w3.x); FMA2(A3b, hv.y, w3.y);
        }

        float2 p, q2;
        p = unpack2(A0a); q2 = unpack2(A0b);
        float gi = a0 + ((p.x + q2.x) + (p.y + q2.y));
        p = unpack2(A1a); q2 = unpack2(A1b);
        float gf = a1 + ((p.x + q2.x) + (p.y + q2.y));
        p = unpack2(A2a); q2 = unpack2(A2b);
        float gg = a2 + ((p.x + q2.x) + (p.y + q2.y));
        p = unpack2(A3a); q2 = unpack2(A3b);
        float go = a3 + ((p.x + q2.x) + (p.y + q2.y));

        float cn = sigf(gf) * c_s[tid] + sigf(gi) * tanhf(gg);
        float hn = sigf(go) * tanhf(cn);
        c_s[tid] = cn;

        float* hout = hbuf + ((t + 1) & 1) * (BB * HH);
        hout[(long)r * HH + J + d] = hn;
        if (t >= SS)
            hseq[(long)(t - SS) * (BB * HH) + (long)r * HH + J + d] = hn;

        // prefetch xp for t+1 BEFORE the barrier (hides DRAM latency)
        if (t + 1 < NSTEP) {
            const float* nxp = (t + 1 < SS) ? (xpE + (long)(t + 1) * (BB * GG))
                                            : (xpD + (long)(t + 1 - SS) * (BB * GG));
            a0 = nxp[xb]; a1 = nxp[xb + 512];
            a2 = nxp[xb + 1024]; a3 = nxp[xb + 1536];
        }

        grid_sync();
    }
}

// ---------------------------------------------------------------------------
// kernel_launch
// ---------------------------------------------------------------------------
extern "C" void kernel_launch(void* const* d_in, const int* in_sizes, int n_in,
                              void* d_out, int out_size) {
    (void)in_sizes; (void)n_in; (void)out_size;
    const int*   src     = (const int*)  d_in[0];
    const int*   tgt     = (const int*)  d_in[1];
    const float* enc_emb = (const float*)d_in[2];
    const float* dec_emb = (const float*)d_in[3];
    const float* enc_Wih = (const float*)d_in[4];
    const float* enc_Whh = (const float*)d_in[5];
    const float* enc_bih = (const float*)d_in[6];
    const float* enc_bhh = (const float*)d_in[7];
    const float* dec_Wih = (const float*)d_in[8];
    const float* dec_Whh = (const float*)d_in[9];
    const float* dec_bih = (const float*)d_in[10];
    const float* dec_bhh = (const float*)d_in[11];
    const float* fc_W    = (const float*)d_in[12];
    const float* fc_b    = (const float*)d_in[13];
    float* out = (float*)d_out;

    float *xpE, *xpD, *hb, *hs;
    __half *whf, *ahf, *embE, *embD, *wihE, *wihD;
    cudaGetSymbolAddress((void**)&xpE, g_xp_enc);
    cudaGetSymbolAddress((void**)&xpD, g_xp_dec);
    cudaGetSymbolAddress((void**)&hb,  g_h);
    cudaGetSymbolAddress((void**)&hs,  g_hseq);
    cudaGetSymbolAddress((void**)&whf, g_Whf);
    cudaGetSymbolAddress((void**)&ahf, g_Ahf);
    cudaGetSymbolAddress((void**)&embE, g_embE);
    cudaGetSymbolAddress((void**)&embD, g_embD);
    cudaGetSymbolAddress((void**)&wihE, g_wihE);
    cudaGetSymbolAddress((void**)&wihD, g_wihD);

    const int recSmem = (WS_FLOATS + HS_FLOATS + 256) * sizeof(float);  // ~166 KB
    cudaFuncSetAttribute(lstm_persistent,
                         cudaFuncAttributeMaxDynamicSharedMemorySize, recSmem);
    const int fcSmem = 3 * FC_STG;                                      // 96 KB
    cudaFuncSetAttribute(fc_f16,
                         cudaFuncAttributeMaxDynamicSharedMemorySize, fcSmem);

    // 1) zero out[:,0,:]
    init_kernel<<<(BB * VV / 4 + 255) / 256, 256>>>(out);

    // 2) fp16 conversions (tables + weights)
    {
        long n;
        n = (long)VV * EE;
        conv_f16<<<(int)((n / 8 + 255) / 256), 256>>>(enc_emb, n, embE, n);
        conv_f16<<<(int)((n / 8 + 255) / 256), 256>>>(dec_emb, n, embD, n);
        n = (long)GG * EE;
        conv_f16<<<(int)((n / 8 + 255) / 256), 256>>>(enc_Wih, n, wihE, n);
        conv_f16<<<(int)((n / 8 + 255) / 256), 256>>>(dec_Wih, n, wihD, n);
        n = (long)VV * HH;
        conv_f16<<<(int)((n / 8 + 255) / 256), 256>>>(fc_W, n, whf, n);
    }

    // 3) xp = emb[tok] @ Wih^T + (bih + bhh)  on fp16 tensor cores
    xp_f16<<<dim3(GG / 128, NENC / 128), 128>>>(
        embE, src, SS, NENC, wihE, enc_bih, enc_bhh, xpE);
    xp_f16<<<dim3(GG / 128, (NDEC + 127) / 128), 128>>>(
        embD, tgt, 32, NDEC, wihD, dec_bih, dec_bhh, xpD);

    // 4) fused persistent recurrence: enc 64 + dec 31 steps, 1 launch
    lstm_persistent<<<RGRID, 256, recSmem>>>(xpE, xpD, enc_Whh, dec_Whh, hb, hs);

    // 5) hseq -> fp16 (padded to MPAD rows with zeros)
    {
        long nElem = (long)NDEC * HH, total = (long)MPAD * HH;
        conv_f16<<<(int)((total / 8 + 255) / 256), 256>>>(hs, nElem, ahf, total);
    }

    // 6) vocab projection on fp16 tensor cores -> out[b][t+1][v]
    fc_f16<<<dim3(VV / 128, MPAD / 128), 256, fcSmem>>>(ahf, whf, fc_b, out);
}

// round 13
// speedup vs baseline: 2.2164x; 1.1196x over previous
#include <cuda_runtime.h>
#include <cuda_fp16.h>
#include <cuda_bf16.h>
#include <cstdint>

// Problem constants
#define BB 64      // batch
#define SS 64      // src length (encoder steps)
#define TD 31      // decoder steps (T-1)
#define EE 256     // embed dim
#define HH 512     // hidden
#define GG 2048    // 4*H gates
#define VV 32000   // vocab
#define NENC (SS*BB)   // 4096 rows
#define NDEC (TD*BB)   // 1984 rows
#define NSTEP (SS+TD)  // 95
#define RGRID 128      // recurrence CTAs (<= SM count -> co-resident)
#define MPAD 2048      // padded hseq rows for fc M tiles

// -------- device scratch (allocation-free rule: __device__ globals) --------
__device__ float g_xp_enc[(size_t)NENC * GG];   // 33.5 MB [t*64+b][g]
__device__ float g_xp_dec[(size_t)NDEC * GG];   // 16.3 MB
__device__ float g_h[2][BB * HH];               // ping-pong hidden state
__device__ float g_hseq[(size_t)NDEC * HH];     // decoder outputs [t*64+b][h]
__device__ __half g_Whf[(size_t)VV * HH];       // 33.5 MB fp16 fc W
__device__ __half g_Ahf[(size_t)MPAD * HH];     // 2 MB fp16 hseq (padded)
__device__ __half g_embE[(size_t)VV * EE];      // 16.4 MB fp16 enc_emb
__device__ __half g_embD[(size_t)VV * EE];      // 16.4 MB fp16 dec_emb
__device__ __half g_wihE[(size_t)GG * EE];      // 1 MB fp16 enc_Wih
__device__ __half g_wihD[(size_t)GG * EE];      // 1 MB fp16 dec_Wih

// grid-barrier state: cumulative counters -> replay-safe without reset
__device__ unsigned g_arrive;
__device__ unsigned g_epoch;

// ---------------------------------------------------------------------------
// init: zero out[:,0,:]  (vectorized; VV % 4 == 0 so float4 stays in-row)
// ---------------------------------------------------------------------------
__global__ void init_kernel(float* __restrict__ out) {
    long idx = ((long)blockIdx.x * 256 + threadIdx.x) * 4;
    if (idx < (long)BB * VV) {
        long b = idx / VV, v = idx - b * VV;
        *(float4*)(out + b * (32L * VV) + v) = make_float4(0.f, 0.f, 0.f, 0.f);
    }
}

// ---------------------------------------------------------------------------
// fp32 -> fp16 conversions
// ---------------------------------------------------------------------------
__device__ __forceinline__ void cv8(const float* s, __half* d, long off) {
    float4 v0 = *(const float4*)(s + off);
    float4 v1 = *(const float4*)(s + off + 4);
    __half h[8];
    h[0] = __float2half_rn(v0.x); h[1] = __float2half_rn(v0.y);
    h[2] = __float2half_rn(v0.z); h[3] = __float2half_rn(v0.w);
    h[4] = __float2half_rn(v1.x); h[5] = __float2half_rn(v1.y);
    h[6] = __float2half_rn(v1.z); h[7] = __float2half_rn(v1.w);
    *(uint4*)(d + off) = *(const uint4*)h;
}

__global__ __launch_bounds__(256) void conv_f16(
    const float* __restrict__ src, long nElem,
    __half* __restrict__ dst, long total)
{
    long i = ((long)blockIdx.x * 256 + threadIdx.x) * 8;
    if (i >= total) return;
    if (i + 8 <= nElem) { cv8(src, dst, i); return; }
    __half h[8];
#pragma unroll
    for (int j = 0; j < 8; ++j)
        h[j] = __float2half_rn((i + j < nElem) ? src[i + j] : 0.f);
    *(uint4*)(dst + i) = *(const uint4*)h;
}

// merged conversion of the 4 xp tables (embE, embD, wihE, wihD)
__global__ __launch_bounds__(256) void conv4_f16(
    const float* __restrict__ s0, const float* __restrict__ s1,
    const float* __restrict__ s2, const float* __restrict__ s3,
    __half* __restrict__ d0, __half* __restrict__ d1,
    __half* __restrict__ d2, __half* __restrict__ d3)
{
    const long VE = (long)VV * EE, GE = (long)GG * EE;
    long i = ((long)blockIdx.x * 256 + threadIdx.x) * 8;
    if (i < VE)                { cv8(s0, d0, i); }
    else if (i < 2 * VE)       { cv8(s1, d1, i - VE); }
    else if (i < 2 * VE + GE)  { cv8(s2, d2, i - 2 * VE); }
    else if (i < 2 * VE + 2 * GE) { cv8(s3, d3, i - 2 * VE - GE); }
}

// ---------------------------------------------------------------------------
// Shared mma/ldmatrix helpers (fp16, m16n8k16, f32 accum)
// ---------------------------------------------------------------------------
__device__ __forceinline__ uint32_t smem_u32(const void* p) {
    uint32_t a;
    asm("{ .reg .u64 t; cvta.to.shared.u64 t, %1; cvt.u32.u64 %0, t; }"
        : "=r"(a) : "l"(p));
    return a;
}
__device__ __forceinline__ void cp16b(uint32_t smem_addr, const void* gmem) {
    asm volatile("cp.async.ca.shared.global [%0], [%1], 16;" :: "r"(smem_addr), "l"(gmem));
}
#define CP_COMMIT() asm volatile("cp.async.commit_group;")
#define CP_WAIT(n)  asm volatile("cp.async.wait_group %0;" :: "n"(n))

#define LDSM4(r, a) \
    asm volatile("ldmatrix.sync.aligned.m8n8.x4.shared.b16 {%0,%1,%2,%3}, [%4];" \
        : "=r"((r)[0]), "=r"((r)[1]), "=r"((r)[2]), "=r"((r)[3]) : "r"(a))

__device__ __forceinline__ void mma_f16(float* d, const uint32_t* a, const uint32_t* b) {
    asm volatile(
        "mma.sync.aligned.m16n8k16.row.col.f32.f16.f16.f32 "
        "{%0,%1,%2,%3}, {%4,%5,%6,%7}, {%8,%9}, {%0,%1,%2,%3};"
        : "+f"(d[0]), "+f"(d[1]), "+f"(d[2]), "+f"(d[3])
        : "r"(a[0]), "r"(a[1]), "r"(a[2]), "r"(a[3]), "r"(b[0]), "r"(b[1]));
}

// swizzled 16B-unit offset for (row, chunk) in a 128x32 fp16 tile (64B rows)
__device__ __forceinline__ uint32_t swz16(int row, int chunk) {
    return (uint32_t)(row * 4 + (chunk ^ ((row >> 1) & 3)));
}

// ---------------------------------------------------------------------------
// fc GEMM: CTA 128x128, 8 warps (4m x 2n), warp tile 32x64.
//   K-chunk 64 (8 chunks), 3-stage cp.async ring, ONE syncthreads per chunk.
//   No min-blocks cap (allow full regs; avoid epilogue spills).
// ---------------------------------------------------------------------------
#define FC_STG 32768             // bytes per stage (A 16KB + B 16KB)

__global__ __launch_bounds__(256) void fc_f16(
    const __half* __restrict__ A, const __half* __restrict__ W,
    const float* __restrict__ bias, float* __restrict__ out)
{
    extern __shared__ __half fsm[];
    const int tid = threadIdx.x, wid = tid >> 5, lane = tid & 31;
    const int wm = wid & 3, wn = wid >> 2;
    const int mBase = blockIdx.y * 128;
    const long nBase = (long)blockIdx.x * 128;
    const uint32_t sb = smem_u32(fsm);

    const int mat = lane >> 3;           // 0..3
    const int abit = mat >> 1, bbit = mat & 1;
    int rA[2], rB[4];
#pragma unroll
    for (int mi = 0; mi < 2; ++mi) rA[mi] = wm * 32 + mi * 16 + (mat & 1) * 8 + (lane & 7);
#pragma unroll
    for (int nj = 0; nj < 4; ++nj) rB[nj] = wn * 64 + nj * 16 + (mat >> 1) * 8 + (lane & 7);

    float acc[2][8][4] = {};

#define FC_STAGE(s, kc) do {                                                \
        uint32_t base = sb + (s) * FC_STG;                                  \
        for (int it = 0; it < 4; ++it) {                                    \
            int idx = it * 256 + tid;          /* 0..1023 */                \
            int row = idx >> 3, ch = idx & 7;                               \
            uint32_t sw = (uint32_t)(row * 8 + (ch ^ (row & 7))) * 16;      \
            cp16b(base + sw,                                                \
                  A + (long)(mBase + row) * HH + (kc) * 64 + ch * 8);       \
            cp16b(base + 16384 + sw,                                        \
                  W + (nBase + row) * (long)HH + (kc) * 64 + ch * 8);       \
        }                                                                   \
        CP_COMMIT();                                                        \
    } while (0)

    FC_STAGE(0, 0);
    FC_STAGE(1, 1);
    int sCur = 0;
    for (int kc = 0; kc < 8; ++kc) {
        if (kc < 7) { CP_WAIT(1); } else { CP_WAIT(0); }
        __syncthreads();                  // chunk kc visible; buf (kc+2)%3 free
        if (kc + 2 < 8) FC_STAGE((sCur + 2 >= 3) ? sCur - 1 : sCur + 2, kc + 2);
        const uint32_t aT = sb + sCur * FC_STG;
        const uint32_t bT = aT + 16384;
#pragma unroll
        for (int ks = 0; ks < 4; ++ks) {
            uint32_t af[2][4], bf[4][4];
#pragma unroll
            for (int mi = 0; mi < 2; ++mi) {
                uint32_t c = (uint32_t)((2 * ks + abit) ^ (rA[mi] & 7));
                LDSM4(af[mi], aT + (uint32_t)(rA[mi] * 8 + c) * 16);
            }
#pragma unroll
            for (int nj = 0; nj < 4; ++nj) {
                uint32_t c = (uint32_t)((2 * ks + bbit) ^ (rB[nj] & 7));
                LDSM4(bf[nj], bT + (uint32_t)(rB[nj] * 8 + c) * 16);
            }
#pragma unroll
            for (int mi = 0; mi < 2; ++mi)
#pragma unroll
                for (int ni = 0; ni < 8; ++ni)
                    mma_f16(acc[mi][ni], af[mi], bf[ni >> 1] + (ni & 1) * 2);
        }
        sCur = (sCur == 2) ? 0 : sCur + 1;
    }
#undef FC_STAGE

    // epilogue: add bias, scatter to out[b][t+1][n]
    const int mTop = mBase + wm * 32 + (lane >> 2);
    const long nCol = nBase + wn * 64 + (lane & 3) * 2;
#pragma unroll
    for (int ni = 0; ni < 8; ++ni) {
        long n = nCol + ni * 8;
        float2 bv = *(const float2*)(bias + n);
#pragma unroll
        for (int mi = 0; mi < 2; ++mi) {
            int m0 = mTop + mi * 16;
            if (m0 < NDEC) {
                int b = m0 & 63, t = m0 >> 6;
                float2 v = make_float2(acc[mi][ni][0] + bv.x, acc[mi][ni][1] + bv.y);
                *(float2*)(out + (long)(b * 32 + t + 1) * VV + n) = v;
            }
            int m1 = m0 + 8;
            if (m1 < NDEC) {
                int b = m1 & 63, t = m1 >> 6;
                float2 v = make_float2(acc[mi][ni][2] + bv.x, acc[mi][ni][3] + bv.y);
                *(float2*)(out + (long)(b * 32 + t + 1) * VV + n) = v;
            }
        }
    }
}

// ---------------------------------------------------------------------------
// xp GEMM (fp16 tensor): xp[r][n] = emb16[tok[r]] . Wih16[n] + bih[n]+bhh[n]
// ---------------------------------------------------------------------------
__global__ __launch_bounds__(128) void xp_f16(
    const __half* __restrict__ emb, const int* __restrict__ tok,
    int tokStride, int nRows,
    const __half* __restrict__ Wih,
    const float* __restrict__ bias0, const float* __restrict__ bias1,
    float* __restrict__ xp)
{
    __shared__ __half sA[2][128 * 32];
    __shared__ __half sB[2][128 * 32];
    __shared__ int stok[128];
    const int tid = threadIdx.x, wid = tid >> 5, lane = tid & 31;
    const int wm = wid & 1, wn = wid >> 1;
    const int mBase = blockIdx.y * 128;
    const int nBase = blockIdx.x * 128;
    const uint32_t sAb = smem_u32(sA), sBb = smem_u32(sB);

    if (tid < 128) {
        int r = mBase + tid;
        if (r >= nRows) r = nRows - 1;
        stok[tid] = tok[(r & 63) * tokStride + (r >> 6)];
    }
    __syncthreads();

    const int mat = lane >> 3;
    const int rowA = wm * 64 + (mat & 1) * 8 + (lane & 7);
    const int swA = (rowA >> 1) & 3;
    const uint32_t aOff0 = (rowA * 4 + (((mat >> 1) + 0) ^ swA)) * 16;
    const uint32_t aOff1 = (rowA * 4 + (((mat >> 1) + 2) ^ swA)) * 16;
    const int rowB = wn * 64 + (mat >> 1) * 8 + (lane & 7);
    const int swB = (rowB >> 1) & 3;
    const uint32_t bOff0 = (rowB * 4 + (((mat & 1) + 0) ^ swB)) * 16;
    const uint32_t bOff1 = (rowB * 4 + (((mat & 1) + 2) ^ swB)) * 16;

    float acc[4][8][4] = {};

#define XP_STAGE(buf, kc) do {                                              \
        for (int it = 0; it < 4; ++it) {                                    \
            int idx = it * 128 + tid;                                       \
            int row = idx >> 2, ch = idx & 3;                               \
            cp16b(sAb + (buf) * 8192 + swz16(row, ch) * 16,                 \
                  emb + (long)stok[row] * EE + (kc) * 32 + ch * 8);         \
            cp16b(sBb + (buf) * 8192 + swz16(row, ch) * 16,                 \
                  Wih + (long)(nBase + row) * EE + (kc) * 32 + ch * 8);     \
        }                                                                   \
        CP_COMMIT();                                                        \
    } while (0)

    XP_STAGE(0, 0);
    for (int kc = 0; kc < 8; ++kc) {
        const int buf = kc & 1;
        __syncthreads();
        if (kc + 1 < 8) XP_STAGE(buf ^ 1, kc + 1);
        if (kc + 1 < 8) { CP_WAIT(1); } else { CP_WAIT(0); }
        __syncthreads();

        const uint32_t aT = sAb + buf * 8192;
        const uint32_t bT = sBb + buf * 8192;
#pragma unroll
        for (int ks = 0; ks < 2; ++ks) {
            const uint32_t ao = ks ? aOff1 : aOff0;
            const uint32_t bo = ks ? bOff1 : bOff0;
            uint32_t af[4][4], bf[4][4];
#pragma unroll
            for (int mi = 0; mi < 4; ++mi)
                LDSM4(af[mi], aT + ao + mi * 1024);
#pragma unroll
            for (int nj = 0; nj < 4; ++nj)
                LDSM4(bf[nj], bT + bo + nj * 1024);
#pragma unroll
            for (int mi = 0; mi < 4; ++mi)
#pragma unroll
                for (int ni = 0; ni < 8; ++ni)
                    mma_f16(acc[mi][ni], af[mi], bf[ni >> 1] + (ni & 1) * 2);
        }
    }
#undef XP_STAGE

    const int mTop = mBase + wm * 64 + (lane >> 2);
    const int nCol = nBase + wn * 64 + (lane & 3) * 2;
#pragma unroll
    for (int ni = 0; ni < 8; ++ni) {
        int n = nCol + ni * 8;
        float2 bv = make_float2(bias0[n] + bias1[n], bias0[n + 1] + bias1[n + 1]);
#pragma unroll
        for (int mi = 0; mi < 4; ++mi) {
            int m0 = mTop + mi * 16;
            if (m0 < nRows) {
                float2 v = make_float2(acc[mi][ni][0] + bv.x, acc[mi][ni][1] + bv.y);
                *(float2*)(xp + (long)m0 * GG + n) = v;
            }
            int m1 = m0 + 8;
            if (m1 < nRows) {
                float2 v = make_float2(acc[mi][ni][2] + bv.x, acc[mi][ni][3] + bv.y);
                *(float2*)(xp + (long)m1 * GG + n) = v;
            }
        }
    }
}

// ---------------------------------------------------------------------------
// Persistent fused LSTM recurrence.
//   R13: 128 thr/CTA, each thread computes 2 batch rows (weight reuse across
//   rows -> 6 LDS per 16 FMA2, FMA2-issue-bound). acq_rel barrier, xp prefetch.
// ---------------------------------------------------------------------------
__device__ __forceinline__ float sigf(float x) { return 1.f / (1.f + __expf(-x)); }

__device__ __forceinline__ void grid_sync() {
    __syncthreads();
    if (threadIdx.x == 0) {
        unsigned t;
        asm volatile("atom.add.acq_rel.gpu.u32 %0, [%1], 1;"
                     : "=r"(t) : "l"(&g_arrive) : "memory");
        unsigned target = t / (unsigned)RGRID + 1u;
        if ((t % (unsigned)RGRID) == (unsigned)(RGRID - 1)) {
            asm volatile("st.release.gpu.u32 [%0], %1;"
                         :: "l"(&g_epoch), "r"(target) : "memory");
        } else {
            unsigned e;
            do {
                asm volatile("ld.acquire.gpu.u32 %0, [%1];"
                             : "=r"(e) : "l"(&g_epoch) : "memory");
            } while (e < target);
        }
    }
    __syncthreads();
}

__device__ __forceinline__ void cp16(float* smem, const float* gmem) {
    unsigned s = (unsigned)__cvta_generic_to_shared(smem);
    asm volatile("cp.async.ca.shared.global [%0], [%1], 16;" :: "r"(s), "l"(gmem));
}

#define FMA2(acc, a, b) \
    asm("fma.rn.f32x2 %0, %1, %2, %0;" : "+l"(acc) : "l"(a), "l"(b))

__device__ __forceinline__ float2 unpack2(unsigned long long v) {
    float2 f;
    asm("mov.b64 {%0, %1}, %2;" : "=f"(f.x), "=f"(f.y) : "l"(v));
    return f;
}
__device__ __forceinline__ float red4(unsigned long long a, unsigned long long b) {
    float2 p = unpack2(a), q = unpack2(b);
    return (p.x + q.x) + (p.y + q.y);
}

#define WS_STRIDE 516
#define WS_FLOATS (16 * WS_STRIDE)
#define HS_FLOATS (64 * WS_STRIDE)

__global__ __launch_bounds__(128, 1) void lstm_persistent(
    const float* __restrict__ xpE, const float* __restrict__ xpD,
    const float* __restrict__ Wenc, const float* __restrict__ Wdec,
    float* __restrict__ hbuf, float* __restrict__ hseq)
{
    extern __shared__ float sm[];
    float* w_s = sm;                    // 16 x 516
    float* h_s = sm + WS_FLOATS;        // 64 x 516
    float* c_s = h_s + HS_FLOATS;       // 256

    const int tid = threadIdx.x;        // 0..127
    const int d   = tid & 3;            // hidden unit within CTA
    const int rr  = tid >> 2;           // 0..31; thread owns rows rr, rr+32
    const int J   = blockIdx.x * 4;     // hidden base

    for (int i = tid; i < 16 * 128; i += 128) {
        int c = i >> 7, q = (i & 127) << 2;
        int row = (c >> 2) * 512 + J + (c & 3);
        *(float4*)(w_s + c * WS_STRIDE + q) = *(const float4*)(Wenc + (long)row * HH + q);
    }
    hbuf[(long)rr * HH + J + d] = 0.f;
    hbuf[(long)(rr + 32) * HH + J + d] = 0.f;
    c_s[tid] = 0.f;
    c_s[tid + 128] = 0.f;
    grid_sync();

    const float* hr1 = h_s + rr * WS_STRIDE;
    const float* hr2 = h_s + (rr + 32) * WS_STRIDE;
    const float* wp0 = w_s + (0  + d) * WS_STRIDE;
    const float* wp1 = w_s + (4  + d) * WS_STRIDE;
    const float* wp2 = w_s + (8  + d) * WS_STRIDE;
    const float* wp3 = w_s + (12 + d) * WS_STRIDE;

    const long xb1 = (long)rr * GG + J + d;
    const long xb2 = (long)(rr + 32) * GG + J + d;
    float a10 = xpE[xb1], a11 = xpE[xb1 + 512], a12 = xpE[xb1 + 1024], a13 = xpE[xb1 + 1536];
    float a20 = xpE[xb2], a21 = xpE[xb2 + 512], a22 = xpE[xb2 + 1024], a23 = xpE[xb2 + 1536];

    for (int t = 0; t < NSTEP; ++t) {
        // stage h[t] into SMEM in two 256-col chunks via cp.async
        const float* hin = hbuf + (t & 1) * (BB * HH);
#pragma unroll
        for (int c = 0; c < 2; ++c) {
#pragma unroll
            for (int i = 0; i < 32; ++i) {
                int idx = i * 128 + tid;                 // 0..4095
                int r2 = idx >> 6, q = (idx & 63) << 2;
                cp16(h_s + r2 * WS_STRIDE + c * 256 + q,
                     hin + r2 * HH + c * 256 + q);
            }
            CP_COMMIT();
        }
        if (t == SS) {
            for (int i = tid; i < 16 * 128; i += 128) {
                int c = i >> 7, q = (i & 127) << 2;
                int row = (c >> 2) * 512 + J + (c & 3);
                *(float4*)(w_s + c * WS_STRIDE + q) = *(const float4*)(Wdec + (long)row * HH + q);
            }
        }

        // 16 packed accumulators: [row r | row r+32] x 4 gates x 2 halves
        unsigned long long B10a = 0, B10b = 0, B11a = 0, B11b = 0;
        unsigned long long B12a = 0, B12b = 0, B13a = 0, B13b = 0;
        unsigned long long B20a = 0, B20b = 0, B21a = 0, B21b = 0;
        unsigned long long B22a = 0, B22b = 0, B23a = 0, B23b = 0;

        CP_WAIT(1);
        __syncthreads();
#pragma unroll 2
        for (int k = 0; k < 256; k += 4) {
            ulonglong2 h1 = *(const ulonglong2*)(hr1 + k);
            ulonglong2 h2 = *(const ulonglong2*)(hr2 + k);
            ulonglong2 w0 = *(const ulonglong2*)(wp0 + k);
            ulonglong2 w1 = *(const ulonglong2*)(wp1 + k);
            ulonglong2 w2 = *(const ulonglong2*)(wp2 + k);
            ulonglong2 w3 = *(const ulonglong2*)(wp3 + k);
            FMA2(B10a, h1.x, w0.x); FMA2(B10b, h1.y, w0.y);
            FMA2(B11a, h1.x, w1.x); FMA2(B11b, h1.y, w1.y);
            FMA2(B12a, h1.x, w2.x); FMA2(B12b, h1.y, w2.y);
            FMA2(B13a, h1.x, w3.x); FMA2(B13b, h1.y, w3.y);
            FMA2(B20a, h2.x, w0.x); FMA2(B20b, h2.y, w0.y);
            FMA2(B21a, h2.x, w1.x); FMA2(B21b, h2.y, w1.y);
            FMA2(B22a, h2.x, w2.x); FMA2(B22b, h2.y, w2.y);
            FMA2(B23a, h2.x, w3.x); FMA2(B23b, h2.y, w3.y);
        }
        CP_WAIT(0);
        __syncthreads();
#pragma unroll 2
        for (int k = 256; k < 512; k += 4) {
            ulonglong2 h1 = *(const ulonglong2*)(hr1 + k);
            ulonglong2 h2 = *(const ulonglong2*)(hr2 + k);
            ulonglong2 w0 = *(const ulonglong2*)(wp0 + k);
            ulonglong2 w1 = *(const ulonglong2*)(wp1 + k);
            ulonglong2 w2 = *(const ulonglong2*)(wp2 + k);
            ulonglong2 w3 = *(const ulonglong2*)(wp3 + k);
            FMA2(B10a, h1.x, w0.x); FMA2(B10b, h1.y, w0.y);
            FMA2(B11a, h1.x, w1.x); FMA2(B11b, h1.y, w1.y);
            FMA2(B12a, h1.x, w2.x); FMA2(B12b, h1.y, w2.y);
            FMA2(B13a, h1.x, w3.x); FMA2(B13b, h1.y, w3.y);
            FMA2(B20a, h2.x, w0.x); FMA2(B20b, h2.y, w0.y);
            FMA2(B21a, h2.x, w1.x); FMA2(B21b, h2.y, w1.y);
            FMA2(B22a, h2.x, w2.x); FMA2(B22b, h2.y, w2.y);
            FMA2(B23a, h2.x, w3.x); FMA2(B23b, h2.y, w3.y);
        }

        // activations (torch order i,f,g,o), c resident in SMEM
        float gi1 = a10 + red4(B10a, B10b), gf1 = a11 + red4(B11a, B11b);
        float gg1 = a12 + red4(B12a, B12b), go1 = a13 + red4(B13a, B13b);
        float gi2 = a20 + red4(B20a, B20b), gf2 = a21 + red4(B21a, B21b);
        float gg2 = a22 + red4(B22a, B22b), go2 = a23 + red4(B23a, B23b);

        float cn1 = sigf(gf1) * c_s[tid] + sigf(gi1) * tanhf(gg1);
        float hn1 = sigf(go1) * tanhf(cn1);
        c_s[tid] = cn1;
        float cn2 = sigf(gf2) * c_s[tid + 128] + sigf(gi2) * tanhf(gg2);
        float hn2 = sigf(go2) * tanhf(cn2);
        c_s[tid + 128] = cn2;

        float* hout = hbuf + ((t + 1) & 1) * (BB * HH);
        hout[(long)rr * HH + J + d] = hn1;
        hout[(long)(rr + 32) * HH + J + d] = hn2;
        if (t >= SS) {
            float* hsq = hseq + (long)(t - SS) * (BB * HH);
            hsq[(long)rr * HH + J + d] = hn1;
            hsq[(long)(rr + 32) * HH + J + d] = hn2;
        }

        // prefetch xp for t+1 BEFORE the barrier (hides DRAM latency)
        if (t + 1 < NSTEP) {
            const float* nxp = (t + 1 < SS) ? (xpE + (long)(t + 1) * (BB * GG))
                                            : (xpD + (long)(t + 1 - SS) * (BB * GG));
            a10 = nxp[xb1]; a11 = nxp[xb1 + 512];
            a12 = nxp[xb1 + 1024]; a13 = nxp[xb1 + 1536];
            a20 = nxp[xb2]; a21 = nxp[xb2 + 512];
            a22 = nxp[xb2 + 1024]; a23 = nxp[xb2 + 1536];
        }

        grid_sync();
    }
}

// ---------------------------------------------------------------------------
// kernel_launch: order matters — lstm_persistent is launch #6 (ncu -s 5 -c 1)
// ---------------------------------------------------------------------------
extern "C" void kernel_launch(void* const* d_in, const int* in_sizes, int n_in,
                              void* d_out, int out_size) {
    (void)in_sizes; (void)n_in; (void)out_size;
    const int*   src     = (const int*)  d_in[0];
    const int*   tgt     = (const int*)  d_in[1];
    const float* enc_emb = (const float*)d_in[2];
    const float* dec_emb = (const float*)d_in[3];
    const float* enc_Wih = (const float*)d_in[4];
    const float* enc_Whh = (const float*)d_in[5];
    const float* enc_bih = (const float*)d_in[6];
    const float* enc_bhh = (const float*)d_in[7];
    const float* dec_Wih = (const float*)d_in[8];
    const float* dec_Whh = (const float*)d_in[9];
    const float* dec_bih = (const float*)d_in[10];
    const float* dec_bhh = (const float*)d_in[11];
    const float* fc_W    = (const float*)d_in[12];
    const float* fc_b    = (const float*)d_in[13];
    float* out = (float*)d_out;

    float *xpE, *xpD, *hb, *hs;
    __half *whf, *ahf, *embE, *embD, *wihE, *wihD;
    cudaGetSymbolAddress((void**)&xpE, g_xp_enc);
    cudaGetSymbolAddress((void**)&xpD, g_xp_dec);
    cudaGetSymbolAddress((void**)&hb,  g_h);
    cudaGetSymbolAddress((void**)&hs,  g_hseq);
    cudaGetSymbolAddress((void**)&whf, g_Whf);
    cudaGetSymbolAddress((void**)&ahf, g_Ahf);
    cudaGetSymbolAddress((void**)&embE, g_embE);
    cudaGetSymbolAddress((void**)&embD, g_embD);
    cudaGetSymbolAddress((void**)&wihE, g_wihE);
    cudaGetSymbolAddress((void**)&wihD, g_wihD);

    const int recSmem = (WS_FLOATS + HS_FLOATS + 256) * sizeof(float);  // ~166 KB
    cudaFuncSetAttribute(lstm_persistent,
                         cudaFuncAttributeMaxDynamicSharedMemorySize, recSmem);
    const int fcSmem = 3 * FC_STG;                                      // 96 KB
    cudaFuncSetAttribute(fc_f16,
                         cudaFuncAttributeMaxDynamicSharedMemorySize, fcSmem);

    // #1 zero out[:,0,:]
    init_kernel<<<(BB * VV / 4 + 255) / 256, 256>>>(out);

    // #2 merged xp-table conversions (embE, embD, wihE, wihD)
    {
        long total = 2L * VV * EE + 2L * GG * EE;
        conv4_f16<<<(int)((total / 8 + 255) / 256), 256>>>(
            enc_emb, dec_emb, enc_Wih, dec_Wih, embE, embD, wihE, wihD);
    }

    // #3, #4 xp GEMMs on fp16 tensor cores
    xp_f16<<<dim3(GG / 128, NENC / 128), 128>>>(
        embE, src, SS, NENC, wihE, enc_bih, enc_bhh, xpE);
    xp_f16<<<dim3(GG / 128, (NDEC + 127) / 128), 128>>>(
        embD, tgt, 32, NDEC, wihD, dec_bih, dec_bhh, xpD);

    // #5 fc_W -> fp16 (independent; placed here so rec is launch #6)
    {
        long n = (long)VV * HH;
        conv_f16<<<(int)((n / 8 + 255) / 256), 256>>>(fc_W, n, whf, n);
    }

    // #6 fused persistent recurrence (PROFILED LAUNCH)
    lstm_persistent<<<RGRID, 128, recSmem>>>(xpE, xpD, enc_Whh, dec_Whh, hb, hs);

    // #7 hseq -> fp16 (padded to MPAD rows with zeros)
    {
        long nElem = (long)NDEC * HH, total = (long)MPAD * HH;
        conv_f16<<<(int)((total / 8 + 255) / 256), 256>>>(hs, nElem, ahf, total);
    }

    // #8 vocab projection on fp16 tensor cores -> out[b][t+1][v]
    fc_f16<<<dim3(VV / 128, MPAD / 128), 256, fcSmem>>>(ahf, whf, fc_b, out);
}

// round 14
// speedup vs baseline: 2.3043x; 1.0397x over previous
#include <cuda_runtime.h>
#include <cuda_fp16.h>
#include <cuda_bf16.h>
#include <cstdint>

// Problem constants
#define BB 64      // batch
#define SS 64      // src length (encoder steps)
#define TD 31      // decoder steps (T-1)
#define EE 256     // embed dim
#define HH 512     // hidden
#define GG 2048    // 4*H gates
#define VV 32000   // vocab
#define NENC (SS*BB)   // 4096 rows
#define NDEC (TD*BB)   // 1984 rows
#define NSTEP (SS+TD)  // 95
#define RGRID 128      // recurrence CTAs (<= SM count -> co-resident)
#define MPAD 2048      // padded hseq rows for fc M tiles

// -------- device scratch (allocation-free rule: __device__ globals) --------
__device__ float g_xp_enc[(size_t)NENC * GG];   // 33.5 MB [t*64+b][g]
__device__ float g_xp_dec[(size_t)NDEC * GG];   // 16.3 MB
__device__ float g_h[2][BB * HH];               // ping-pong hidden state
__device__ float g_hseq[(size_t)NDEC * HH];     // decoder outputs [t*64+b][h]
__device__ __half g_Whf[(size_t)VV * HH];       // 33.5 MB fp16 fc W
__device__ __half g_Ahf[(size_t)MPAD * HH];     // 2 MB fp16 hseq (padded)
__device__ __half g_embE[(size_t)VV * EE];      // 16.4 MB fp16 enc_emb
__device__ __half g_embD[(size_t)VV * EE];      // 16.4 MB fp16 dec_emb
__device__ __half g_wihE[(size_t)GG * EE];      // 1 MB fp16 enc_Wih
__device__ __half g_wihD[(size_t)GG * EE];      // 1 MB fp16 dec_Wih

// grid-barrier state: cumulative counters -> replay-safe without reset
__device__ unsigned g_arrive;
__device__ unsigned g_epoch;

// ---------------------------------------------------------------------------
// init: zero out[:,0,:]
// ---------------------------------------------------------------------------
__global__ void init_kernel(float* __restrict__ out) {
    long idx = ((long)blockIdx.x * 256 + threadIdx.x) * 4;
    if (idx < (long)BB * VV) {
        long b = idx / VV, v = idx - b * VV;
        *(float4*)(out + b * (32L * VV) + v) = make_float4(0.f, 0.f, 0.f, 0.f);
    }
}

// ---------------------------------------------------------------------------
// fp32 -> fp16 conversions
// ---------------------------------------------------------------------------
__device__ __forceinline__ void cv8(const float* s, __half* d, long off) {
    float4 v0 = *(const float4*)(s + off);
    float4 v1 = *(const float4*)(s + off + 4);
    __half h[8];
    h[0] = __float2half_rn(v0.x); h[1] = __float2half_rn(v0.y);
    h[2] = __float2half_rn(v0.z); h[3] = __float2half_rn(v0.w);
    h[4] = __float2half_rn(v1.x); h[5] = __float2half_rn(v1.y);
    h[6] = __float2half_rn(v1.z); h[7] = __float2half_rn(v1.w);
    *(uint4*)(d + off) = *(const uint4*)h;
}

__global__ __launch_bounds__(256) void conv_f16(
    const float* __restrict__ src, long nElem,
    __half* __restrict__ dst, long total)
{
    long i = ((long)blockIdx.x * 256 + threadIdx.x) * 8;
    if (i >= total) return;
    if (i + 8 <= nElem) { cv8(src, dst, i); return; }
    __half h[8];
#pragma unroll
    for (int j = 0; j < 8; ++j)
        h[j] = __float2half_rn((i + j < nElem) ? src[i + j] : 0.f);
    *(uint4*)(dst + i) = *(const uint4*)h;
}

__global__ __launch_bounds__(256) void conv4_f16(
    const float* __restrict__ s0, const float* __restrict__ s1,
    const float* __restrict__ s2, const float* __restrict__ s3,
    __half* __restrict__ d0, __half* __restrict__ d1,
    __half* __restrict__ d2, __half* __restrict__ d3)
{
    const long VE = (long)VV * EE, GE = (long)GG * EE;
    long i = ((long)blockIdx.x * 256 + threadIdx.x) * 8;
    if (i < VE)                { cv8(s0, d0, i); }
    else if (i < 2 * VE)       { cv8(s1, d1, i - VE); }
    else if (i < 2 * VE + GE)  { cv8(s2, d2, i - 2 * VE); }
    else if (i < 2 * VE + 2 * GE) { cv8(s3, d3, i - 2 * VE - GE); }
}

// ---------------------------------------------------------------------------
// Shared mma/ldmatrix helpers (fp16, m16n8k16, f32 accum)
// ---------------------------------------------------------------------------
__device__ __forceinline__ uint32_t smem_u32(const void* p) {
    uint32_t a;
    asm("{ .reg .u64 t; cvta.to.shared.u64 t, %1; cvt.u32.u64 %0, t; }"
        : "=r"(a) : "l"(p));
    return a;
}
__device__ __forceinline__ void cp16b(uint32_t smem_addr, const void* gmem) {
    asm volatile("cp.async.ca.shared.global [%0], [%1], 16;" :: "r"(smem_addr), "l"(gmem));
}
#define CP_COMMIT() asm volatile("cp.async.commit_group;")
#define CP_WAIT(n)  asm volatile("cp.async.wait_group %0;" :: "n"(n))

#define LDSM4(r, a) \
    asm volatile("ldmatrix.sync.aligned.m8n8.x4.shared.b16 {%0,%1,%2,%3}, [%4];" \
        : "=r"((r)[0]), "=r"((r)[1]), "=r"((r)[2]), "=r"((r)[3]) : "r"(a))

__device__ __forceinline__ void mma_f16(float* d, const uint32_t* a, const uint32_t* b) {
    asm volatile(
        "mma.sync.aligned.m16n8k16.row.col.f32.f16.f16.f32 "
        "{%0,%1,%2,%3}, {%4,%5,%6,%7}, {%8,%9}, {%0,%1,%2,%3};"
        : "+f"(d[0]), "+f"(d[1]), "+f"(d[2]), "+f"(d[3])
        : "r"(a[0]), "r"(a[1]), "r"(a[2]), "r"(a[3]), "r"(b[0]), "r"(b[1]));
}

// swizzled 16B-unit offset for (row, chunk) in a 128x32 fp16 tile (64B rows)
__device__ __forceinline__ uint32_t swz16(int row, int chunk) {
    return (uint32_t)(row * 4 + (chunk ^ ((row >> 1) & 3)));
}

// ---------------------------------------------------------------------------
// fc GEMM: CTA 128x128, 8 warps (4m x 2n), warp tile 32x64.
//   K-chunk 64 (8 chunks), 3-stage cp.async ring.
//   R14: smem-staged epilogue -> fully coalesced STG.128 output writes.
// ---------------------------------------------------------------------------
#define FC_STG 32768             // bytes per stage (A 16KB + B 16KB)
#define EP_STRIDE 136            // fp32 epilogue smem row stride

__global__ __launch_bounds__(256) void fc_f16(
    const __half* __restrict__ A, const __half* __restrict__ W,
    const float* __restrict__ bias, float* __restrict__ out)
{
    extern __shared__ __half fsm[];
    const int tid = threadIdx.x, wid = tid >> 5, lane = tid & 31;
    const int wm = wid & 3, wn = wid >> 2;
    const int mBase = blockIdx.y * 128;
    const long nBase = (long)blockIdx.x * 128;
    const uint32_t sb = smem_u32(fsm);

    const int mat = lane >> 3;           // 0..3
    const int abit = mat >> 1, bbit = mat & 1;
    int rA[2], rB[4];
#pragma unroll
    for (int mi = 0; mi < 2; ++mi) rA[mi] = wm * 32 + mi * 16 + (mat & 1) * 8 + (lane & 7);
#pragma unroll
    for (int nj = 0; nj < 4; ++nj) rB[nj] = wn * 64 + nj * 16 + (mat >> 1) * 8 + (lane & 7);

    float acc[2][8][4] = {};

#define FC_STAGE(s, kc) do {                                                \
        uint32_t base = sb + (s) * FC_STG;                                  \
        for (int it = 0; it < 4; ++it) {                                    \
            int idx = it * 256 + tid;          /* 0..1023 */                \
            int row = idx >> 3, ch = idx & 7;                               \
            uint32_t sw = (uint32_t)(row * 8 + (ch ^ (row & 7))) * 16;      \
            cp16b(base + sw,                                                \
                  A + (long)(mBase + row) * HH + (kc) * 64 + ch * 8);       \
            cp16b(base + 16384 + sw,                                        \
                  W + (nBase + row) * (long)HH + (kc) * 64 + ch * 8);       \
        }                                                                   \
        CP_COMMIT();                                                        \
    } while (0)

    FC_STAGE(0, 0);
    FC_STAGE(1, 1);
    int sCur = 0;
    for (int kc = 0; kc < 8; ++kc) {
        if (kc < 7) { CP_WAIT(1); } else { CP_WAIT(0); }
        __syncthreads();                  // chunk kc visible; buf (kc+2)%3 free
        if (kc + 2 < 8) FC_STAGE((sCur + 2 >= 3) ? sCur - 1 : sCur + 2, kc + 2);
        const uint32_t aT = sb + sCur * FC_STG;
        const uint32_t bT = aT + 16384;
#pragma unroll
        for (int ks = 0; ks < 4; ++ks) {
            uint32_t af[2][4], bf[4][4];
#pragma unroll
            for (int mi = 0; mi < 2; ++mi) {
                uint32_t c = (uint32_t)((2 * ks + abit) ^ (rA[mi] & 7));
                LDSM4(af[mi], aT + (uint32_t)(rA[mi] * 8 + c) * 16);
            }
#pragma unroll
            for (int nj = 0; nj < 4; ++nj) {
                uint32_t c = (uint32_t)((2 * ks + bbit) ^ (rB[nj] & 7));
                LDSM4(bf[nj], bT + (uint32_t)(rB[nj] * 8 + c) * 16);
            }
#pragma unroll
            for (int mi = 0; mi < 2; ++mi)
#pragma unroll
                for (int ni = 0; ni < 8; ++ni)
                    mma_f16(acc[mi][ni], af[mi], bf[ni >> 1] + (ni & 1) * 2);
        }
        sCur = (sCur == 2) ? 0 : sCur + 1;
    }
#undef FC_STAGE

    // ---- staged epilogue: acc(+bias) -> smem tile -> coalesced STG.128 ----
    __syncthreads();                       // pipeline fully drained by all warps
    float* sOut = (float*)fsm;             // reuse stage smem: 128 x EP_STRIDE
    {
        const int mRow = wm * 32 + (lane >> 2);        // local row of acc[.][.][0..1]
        const int nLoc0 = wn * 64 + (lane & 3) * 2;
#pragma unroll
        for (int ni = 0; ni < 8; ++ni) {
            int nl = nLoc0 + ni * 8;
            float2 bv = *(const float2*)(bias + nBase + nl);
#pragma unroll
            for (int mi = 0; mi < 2; ++mi) {
                int r0 = mRow + mi * 16;
                *(float2*)(sOut + r0 * EP_STRIDE + nl) =
                    make_float2(acc[mi][ni][0] + bv.x, acc[mi][ni][1] + bv.y);
                *(float2*)(sOut + (r0 + 8) * EP_STRIDE + nl) =
                    make_float2(acc[mi][ni][2] + bv.x, acc[mi][ni][3] + bv.y);
            }
        }
    }
    __syncthreads();
    // each warp streams 16 rows, 128 floats per row, contiguous STG.128
#pragma unroll
    for (int i = 0; i < 16; ++i) {
        int r = wid * 16 + i;
        int m = mBase + r;
        if (m < NDEC) {
            int b = m & 63, t = m >> 6;
            float4 v = *(const float4*)(sOut + r * EP_STRIDE + lane * 4);
            *(float4*)(out + (long)(b * 32 + t + 1) * VV + nBase + lane * 4) = v;
        }
    }
}

// ---------------------------------------------------------------------------
// xp GEMM (fp16 tensor): xp[r][n] = emb16[tok[r]] . Wih16[n] + bih[n]+bhh[n]
// ---------------------------------------------------------------------------
__global__ __launch_bounds__(128) void xp_f16(
    const __half* __restrict__ emb, const int* __restrict__ tok,
    int tokStride, int nRows,
    const __half* __restrict__ Wih,
    const float* __restrict__ bias0, const float* __restrict__ bias1,
    float* __restrict__ xp)
{
    __shared__ __half sA[2][128 * 32];
    __shared__ __half sB[2][128 * 32];
    __shared__ int stok[128];
    const int tid = threadIdx.x, wid = tid >> 5, lane = tid & 31;
    const int wm = wid & 1, wn = wid >> 1;
    const int mBase = blockIdx.y * 128;
    const int nBase = blockIdx.x * 128;
    const uint32_t sAb = smem_u32(sA), sBb = smem_u32(sB);

    if (tid < 128) {
        int r = mBase + tid;
        if (r >= nRows) r = nRows - 1;
        stok[tid] = tok[(r & 63) * tokStride + (r >> 6)];
    }
    __syncthreads();

    const int mat = lane >> 3;
    const int rowA = wm * 64 + (mat & 1) * 8 + (lane & 7);
    const int swA = (rowA >> 1) & 3;
    const uint32_t aOff0 = (rowA * 4 + (((mat >> 1) + 0) ^ swA)) * 16;
    const uint32_t aOff1 = (rowA * 4 + (((mat >> 1) + 2) ^ swA)) * 16;
    const int rowB = wn * 64 + (mat >> 1) * 8 + (lane & 7);
    const int swB = (rowB >> 1) & 3;
    const uint32_t bOff0 = (rowB * 4 + (((mat & 1) + 0) ^ swB)) * 16;
    const uint32_t bOff1 = (rowB * 4 + (((mat & 1) + 2) ^ swB)) * 16;

    float acc[4][8][4] = {};

#define XP_STAGE(buf, kc) do {                                              \
        for (int it = 0; it < 4; ++it) {                                    \
            int idx = it * 128 + tid;                                       \
            int row = idx >> 2, ch = idx & 3;                               \
            cp16b(sAb + (buf) * 8192 + swz16(row, ch) * 16,                 \
                  emb + (long)stok[row] * EE + (kc) * 32 + ch * 8);         \
            cp16b(sBb + (buf) * 8192 + swz16(row, ch) * 16,                 \
                  Wih + (long)(nBase + row) * EE + (kc) * 32 + ch * 8);     \
        }                                                                   \
        CP_COMMIT();                                                        \
    } while (0)

    XP_STAGE(0, 0);
    for (int kc = 0; kc < 8; ++kc) {
        const int buf = kc & 1;
        __syncthreads();
        if (kc + 1 < 8) XP_STAGE(buf ^ 1, kc + 1);
        if (kc + 1 < 8) { CP_WAIT(1); } else { CP_WAIT(0); }
        __syncthreads();

        const uint32_t aT = sAb + buf * 8192;
        const uint32_t bT = sBb + buf * 8192;
#pragma unroll
        for (int ks = 0; ks < 2; ++ks) {
            const uint32_t ao = ks ? aOff1 : aOff0;
            const uint32_t bo = ks ? bOff1 : bOff0;
            uint32_t af[4][4], bf[4][4];
#pragma unroll
            for (int mi = 0; mi < 4; ++mi)
                LDSM4(af[mi], aT + ao + mi * 1024);
#pragma unroll
            for (int nj = 0; nj < 4; ++nj)
                LDSM4(bf[nj], bT + bo + nj * 1024);
#pragma unroll
            for (int mi = 0; mi < 4; ++mi)
#pragma unroll
                for (int ni = 0; ni < 8; ++ni)
                    mma_f16(acc[mi][ni], af[mi], bf[ni >> 1] + (ni & 1) * 2);
        }
    }
#undef XP_STAGE

    const int mTop = mBase + wm * 64 + (lane >> 2);
    const int nCol = nBase + wn * 64 + (lane & 3) * 2;
#pragma unroll
    for (int ni = 0; ni < 8; ++ni) {
        int n = nCol + ni * 8;
        float2 bv = make_float2(bias0[n] + bias1[n], bias0[n + 1] + bias1[n + 1]);
#pragma unroll
        for (int mi = 0; mi < 4; ++mi) {
            int m0 = mTop + mi * 16;
            if (m0 < nRows) {
                float2 v = make_float2(acc[mi][ni][0] + bv.x, acc[mi][ni][1] + bv.y);
                *(float2*)(xp + (long)m0 * GG + n) = v;
            }
            int m1 = m0 + 8;
            if (m1 < nRows) {
                float2 v = make_float2(acc[mi][ni][2] + bv.x, acc[mi][ni][3] + bv.y);
                *(float2*)(xp + (long)m1 * GG + n) = v;
            }
        }
    }
}

// ---------------------------------------------------------------------------
// Persistent fused LSTM recurrence (unchanged from R13)
// ---------------------------------------------------------------------------
__device__ __forceinline__ float sigf(float x) { return 1.f / (1.f + __expf(-x)); }

__device__ __forceinline__ void grid_sync() {
    __syncthreads();
    if (threadIdx.x == 0) {
        unsigned t;
        asm volatile("atom.add.acq_rel.gpu.u32 %0, [%1], 1;"
                     : "=r"(t) : "l"(&g_arrive) : "memory");
        unsigned target = t / (unsigned)RGRID + 1u;
        if ((t % (unsigned)RGRID) == (unsigned)(RGRID - 1)) {
            asm volatile("st.release.gpu.u32 [%0], %1;"
                         :: "l"(&g_epoch), "r"(target) : "memory");
        } else {
            unsigned e;
            do {
                asm volatile("ld.acquire.gpu.u32 %0, [%1];"
                             : "=r"(e) : "l"(&g_epoch) : "memory");
            } while (e < target);
        }
    }
    __syncthreads();
}

__device__ __forceinline__ void cp16(float* smem, const float* gmem) {
    unsigned s = (unsigned)__cvta_generic_to_shared(smem);
    asm volatile("cp.async.ca.shared.global [%0], [%1], 16;" :: "r"(s), "l"(gmem));
}

#define FMA2(acc, a, b) \
    asm("fma.rn.f32x2 %0, %1, %2, %0;" : "+l"(acc) : "l"(a), "l"(b))

__device__ __forceinline__ float2 unpack2(unsigned long long v) {
    float2 f;
    asm("mov.b64 {%0, %1}, %2;" : "=f"(f.x), "=f"(f.y) : "l"(v));
    return f;
}
__device__ __forceinline__ float red4(unsigned long long a, unsigned long long b) {
    float2 p = unpack2(a), q = unpack2(b);
    return (p.x + q.x) + (p.y + q.y);
}

#define WS_STRIDE 516
#define WS_FLOATS (16 * WS_STRIDE)
#define HS_FLOATS (64 * WS_STRIDE)

__global__ __launch_bounds__(128, 1) void lstm_persistent(
    const float* __restrict__ xpE, const float* __restrict__ xpD,
    const float* __restrict__ Wenc, const float* __restrict__ Wdec,
    float* __restrict__ hbuf, float* __restrict__ hseq)
{
    extern __shared__ float sm[];
    float* w_s = sm;                    // 16 x 516
    float* h_s = sm + WS_FLOATS;        // 64 x 516
    float* c_s = h_s + HS_FLOATS;       // 256

    const int tid = threadIdx.x;        // 0..127
    const int d   = tid & 3;            // hidden unit within CTA
    const int rr  = tid >> 2;           // 0..31; thread owns rows rr, rr+32
    const int J   = blockIdx.x * 4;     // hidden base

    for (int i = tid; i < 16 * 128; i += 128) {
        int c = i >> 7, q = (i & 127) << 2;
        int row = (c >> 2) * 512 + J + (c & 3);
        *(float4*)(w_s + c * WS_STRIDE + q) = *(const float4*)(Wenc + (long)row * HH + q);
    }
    hbuf[(long)rr * HH + J + d] = 0.f;
    hbuf[(long)(rr + 32) * HH + J + d] = 0.f;
    c_s[tid] = 0.f;
    c_s[tid + 128] = 0.f;
    grid_sync();

    const float* hr1 = h_s + rr * WS_STRIDE;
    const float* hr2 = h_s + (rr + 32) * WS_STRIDE;
    const float* wp0 = w_s + (0  + d) * WS_STRIDE;
    const float* wp1 = w_s + (4  + d) * WS_STRIDE;
    const float* wp2 = w_s + (8  + d) * WS_STRIDE;
    const float* wp3 = w_s + (12 + d) * WS_STRIDE;

    const long xb1 = (long)rr * GG + J + d;
    const long xb2 = (long)(rr + 32) * GG + J + d;
    float a10 = xpE[xb1], a11 = xpE[xb1 + 512], a12 = xpE[xb1 + 1024], a13 = xpE[xb1 + 1536];
    float a20 = xpE[xb2], a21 = xpE[xb2 + 512], a22 = xpE[xb2 + 1024], a23 = xpE[xb2 + 1536];

    for (int t = 0; t < NSTEP; ++t) {
        const float* hin = hbuf + (t & 1) * (BB * HH);
#pragma unroll
        for (int c = 0; c < 2; ++c) {
#pragma unroll
            for (int i = 0; i < 32; ++i) {
                int idx = i * 128 + tid;                 // 0..4095
                int r2 = idx >> 6, q = (idx & 63) << 2;
                cp16(h_s + r2 * WS_STRIDE + c * 256 + q,
                     hin + r2 * HH + c * 256 + q);
            }
            CP_COMMIT();
        }
        if (t == SS) {
            for (int i = tid; i < 16 * 128; i += 128) {
                int c = i >> 7, q = (i & 127) << 2;
                int row = (c >> 2) * 512 + J + (c & 3);
                *(float4*)(w_s + c * WS_STRIDE + q) = *(const float4*)(Wdec + (long)row * HH + q);
            }
        }

        unsigned long long B10a = 0, B10b = 0, B11a = 0, B11b = 0;
        unsigned long long B12a = 0, B12b = 0, B13a = 0, B13b = 0;
        unsigned long long B20a = 0, B20b = 0, B21a = 0, B21b = 0;
        unsigned long long B22a = 0, B22b = 0, B23a = 0, B23b = 0;

        CP_WAIT(1);
        __syncthreads();
#pragma unroll 2
        for (int k = 0; k < 256; k += 4) {
            ulonglong2 h1 = *(const ulonglong2*)(hr1 + k);
            ulonglong2 h2 = *(const ulonglong2*)(hr2 + k);
            ulonglong2 w0 = *(const ulonglong2*)(wp0 + k);
            ulonglong2 w1 = *(const ulonglong2*)(wp1 + k);
            ulonglong2 w2 = *(const ulonglong2*)(wp2 + k);
            ulonglong2 w3 = *(const ulonglong2*)(wp3 + k);
            FMA2(B10a, h1.x, w0.x); FMA2(B10b, h1.y, w0.y);
            FMA2(B11a, h1.x, w1.x); FMA2(B11b, h1.y, w1.y);
            FMA2(B12a, h1.x, w2.x); FMA2(B12b, h1.y, w2.y);
            FMA2(B13a, h1.x, w3.x); FMA2(B13b, h1.y, w3.y);
            FMA2(B20a, h2.x, w0.x); FMA2(B20b, h2.y, w0.y);
            FMA2(B21a, h2.x, w1.x); FMA2(B21b, h2.y, w1.y);
            FMA2(B22a, h2.x, w2.x); FMA2(B22b, h2.y, w2.y);
            FMA2(B23a, h2.x, w3.x); FMA2(B23b, h2.y, w3.y);
        }
        CP_WAIT(0);
        __syncthreads();
#pragma unroll 2
        for (int k = 256; k < 512; k += 4) {
            ulonglong2 h1 = *(const ulonglong2*)(hr1 + k);
            ulonglong2 h2 = *(const ulonglong2*)(hr2 + k);
            ulonglong2 w0 = *(const ulonglong2*)(wp0 + k);
            ulonglong2 w1 = *(const ulonglong2*)(wp1 + k);
            ulonglong2 w2 = *(const ulonglong2*)(wp2 + k);
            ulonglong2 w3 = *(const ulonglong2*)(wp3 + k);
            FMA2(B10a, h1.x, w0.x); FMA2(B10b, h1.y, w0.y);
            FMA2(B11a, h1.x, w1.x); FMA2(B11b, h1.y, w1.y);
            FMA2(B12a, h1.x, w2.x); FMA2(B12b, h1.y, w2.y);
            FMA2(B13a, h1.x, w3.x); FMA2(B13b, h1.y, w3.y);
            FMA2(B20a, h2.x, w0.x); FMA2(B20b, h2.y, w0.y);
            FMA2(B21a, h2.x, w1.x); FMA2(B21b, h2.y, w1.y);
            FMA2(B22a, h2.x, w2.x); FMA2(B22b, h2.y, w2.y);
            FMA2(B23a, h2.x, w3.x); FMA2(B23b, h2.y, w3.y);
        }

        float gi1 = a10 + red4(B10a, B10b), gf1 = a11 + red4(B11a, B11b);
        float gg1 = a12 + red4(B12a, B12b), go1 = a13 + red4(B13a, B13b);
        float gi2 = a20 + red4(B20a, B20b), gf2 = a21 + red4(B21a, B21b);
        float gg2 = a22 + red4(B22a, B22b), go2 = a23 + red4(B23a, B23b);

        float cn1 = sigf(gf1) * c_s[tid] + sigf(gi1) * tanhf(gg1);
        float hn1 = sigf(go1) * tanhf(cn1);
        c_s[tid] = cn1;
        float cn2 = sigf(gf2) * c_s[tid + 128] + sigf(gi2) * tanhf(gg2);
        float hn2 = sigf(go2) * tanhf(cn2);
        c_s[tid + 128] = cn2;

        float* hout = hbuf + ((t + 1) & 1) * (BB * HH);
        hout[(long)rr * HH + J + d] = hn1;
        hout[(long)(rr + 32) * HH + J + d] = hn2;
        if (t >= SS) {
            float* hsq = hseq + (long)(t - SS) * (BB * HH);
            hsq[(long)rr * HH + J + d] = hn1;
            hsq[(long)(rr + 32) * HH + J + d] = hn2;
        }

        if (t + 1 < NSTEP) {
            const float* nxp = (t + 1 < SS) ? (xpE + (long)(t + 1) * (BB * GG))
                                            : (xpD + (long)(t + 1 - SS) * (BB * GG));
            a10 = nxp[xb1]; a11 = nxp[xb1 + 512];
            a12 = nxp[xb1 + 1024]; a13 = nxp[xb1 + 1536];
            a20 = nxp[xb2]; a21 = nxp[xb2 + 512];
            a22 = nxp[xb2 + 1024]; a23 = nxp[xb2 + 1536];
        }

        grid_sync();
    }
}

// ---------------------------------------------------------------------------
// kernel_launch: rec is MY launch #4 (profiler lands there per R13 evidence)
// ---------------------------------------------------------------------------
extern "C" void kernel_launch(void* const* d_in, const int* in_sizes, int n_in,
                              void* d_out, int out_size) {
    (void)in_sizes; (void)n_in; (void)out_size;
    const int*   src     = (const int*)  d_in[0];
    const int*   tgt     = (const int*)  d_in[1];
    const float* enc_emb = (const float*)d_in[2];
    const float* dec_emb = (const float*)d_in[3];
    const float* enc_Wih = (const float*)d_in[4];
    const float* enc_Whh = (const float*)d_in[5];
    const float* enc_bih = (const float*)d_in[6];
    const float* enc_bhh = (const float*)d_in[7];
    const float* dec_Wih = (const float*)d_in[8];
    const float* dec_Whh = (const float*)d_in[9];
    const float* dec_bih = (const float*)d_in[10];
    const float* dec_bhh = (const float*)d_in[11];
    const float* fc_W    = (const float*)d_in[12];
    const float* fc_b    = (const float*)d_in[13];
    float* out = (float*)d_out;

    float *xpE, *xpD, *hb, *hs;
    __half *whf, *ahf, *embE, *embD, *wihE, *wihD;
    cudaGetSymbolAddress((void**)&xpE, g_xp_enc);
    cudaGetSymbolAddress((void**)&xpD, g_xp_dec);
    cudaGetSymbolAddress((void**)&hb,  g_h);
    cudaGetSymbolAddress((void**)&hs,  g_hseq);
    cudaGetSymbolAddress((void**)&whf, g_Whf);
    cudaGetSymbolAddress((void**)&ahf, g_Ahf);
    cudaGetSymbolAddress((void**)&embE, g_embE);
    cudaGetSymbolAddress((void**)&embD, g_embD);
    cudaGetSymbolAddress((void**)&wihE, g_wihE);
    cudaGetSymbolAddress((void**)&wihD, g_wihD);

    const int recSmem = (WS_FLOATS + HS_FLOATS + 256) * sizeof(float);  // ~166 KB
    cudaFuncSetAttribute(lstm_persistent,
                         cudaFuncAttributeMaxDynamicSharedMemorySize, recSmem);
    const int fcSmem = 3 * FC_STG;                                      // 96 KB
    cudaFuncSetAttribute(fc_f16,
                         cudaFuncAttributeMaxDynamicSharedMemorySize, fcSmem);

    // #1 merged xp-table conversions (embE, embD, wihE, wihD)
    {
        long total = 2L * VV * EE + 2L * GG * EE;
        conv4_f16<<<(int)((total / 8 + 255) / 256), 256>>>(
            enc_emb, dec_emb, enc_Wih, dec_Wih, embE, embD, wihE, wihD);
    }

    // #2, #3 xp GEMMs on fp16 tensor cores
    xp_f16<<<dim3(GG / 128, NENC / 128), 128>>>(
        embE, src, SS, NENC, wihE, enc_bih, enc_bhh, xpE);
    xp_f16<<<dim3(GG / 128, (NDEC + 127) / 128), 128>>>(
        embD, tgt, 32, NDEC, wihD, dec_bih, dec_bhh, xpD);

    // #4 fused persistent recurrence (PROFILED LAUNCH)
    lstm_persistent<<<RGRID, 128, recSmem>>>(xpE, xpD, enc_Whh, dec_Whh, hb, hs);

    // #5 zero out[:,0,:] (independent; only needs to precede fc)
    init_kernel<<<(BB * VV / 4 + 255) / 256, 256>>>(out);

    // #6 fc_W -> fp16
    {
        long n = (long)VV * HH;
        conv_f16<<<(int)((n / 8 + 255) / 256), 256>>>(fc_W, n, whf, n);
    }

    // #7 hseq -> fp16 (padded to MPAD rows with zeros)
    {
        long nElem = (long)NDEC * HH, total = (long)MPAD * HH;
        conv_f16<<<(int)((total / 8 + 255) / 256), 256>>>(hs, nElem, ahf, total);
    }

    // #8 vocab projection on fp16 tensor cores -> out[b][t+1][v]
    fc_f16<<<dim3(VV / 128, MPAD / 128), 256, fcSmem>>>(ahf, whf, fc_b, out);
}